// round 6
// baseline (speedup 1.0000x reference)
#include <cuda_runtime.h>
#include <cuda_fp16.h>
#include <cstdint>

// ============================================================================
// SpikingNetwork, T=10. B=512, input=3072, hidden=2048, out=512
// Single-limb fp16 mma.sync GEMMs (spikes exactly 1.0 in fp16 -> products
// exact; weight rounding err ~2e-4 rms) + threshold-margin flagging + exact
// sequential fp32 recompute of flagged elements (reference order).
// tcgen05 unavailable: harness targets sm_100 (no 'a').
// ============================================================================

#define NB   512
#define NIN  3072
#define NHID 2048
#define NOUT 512
#define NT   10
#define NM   (NT * NB)     // 5120

#define MARGIN_V 3.0e-3f
#define MARGIN_O 2.5e-3f
#define CAPS 131072
#define CAPO 131072

__device__ __align__(16) __half g_Pre [NM * NIN];     // [m=(t,b)][j]
__device__ __align__(16) __half g_S   [NM * NHID];    // [m=(t,b)][h]
__device__ __align__(16) __half g_WinH [NHID * NIN];
__device__ __align__(16) __half g_WoutH[NOUT * NHID];
__device__ float    g_H[NM * NHID];
__device__ float    g_O[NM * NOUT];
__device__ uint16_t g_jmask[NB * NIN];
__device__ uint16_t g_smask[NB * NHID];
__device__ uint32_t g_k0[NT];
__device__ uint32_t g_k1[NT];
__device__ int      g_nflagS;
__device__ int      g_flagS[CAPS];
__device__ int      g_nflagO;
__device__ int      g_flagO[CAPO];

// ---------------- threefry2x32 (JAX-exact, 20 rounds) -----------------------
__device__ __forceinline__ uint32_t rotl32(uint32_t x, int r) {
    return __funnelshift_l(x, x, r);
}
__device__ __forceinline__ void threefry2x32(uint32_t k0, uint32_t k1,
                                             uint32_t x0, uint32_t x1,
                                             uint32_t& o0, uint32_t& o1) {
    uint32_t ks2 = k0 ^ k1 ^ 0x1BD11BDAu;
    x0 += k0; x1 += k1;
#define TF_R(r) { x0 += x1; x1 = rotl32(x1, (r)); x1 ^= x0; }
    TF_R(13) TF_R(15) TF_R(26) TF_R(6)
    x0 += k1;  x1 += ks2 + 1u;
    TF_R(17) TF_R(29) TF_R(16) TF_R(24)
    x0 += ks2; x1 += k0 + 2u;
    TF_R(13) TF_R(15) TF_R(26) TF_R(6)
    x0 += k0;  x1 += k1 + 3u;
    TF_R(17) TF_R(29) TF_R(16) TF_R(24)
    x0 += k1;  x1 += ks2 + 4u;
    TF_R(13) TF_R(15) TF_R(26) TF_R(6)
    x0 += ks2; x1 += k0 + 5u;
#undef TF_R
    o0 = x0; o1 = x1;
}

// ---------------- XLA logistic ----------------------------------------------
__device__ __forceinline__ float xla_tanh_f32(float x) {
    const float kClamp = 7.90531110763549805f;
    float ax = fabsf(x);
    float xc = fminf(fmaxf(x, -kClamp), kClamp);
    float x2 = __fmul_rn(xc, xc);
    float p;
    p = __fadd_rn(__fmul_rn(x2, -2.76076847742355e-16f), 2.00018790482477e-13f);
    p = __fadd_rn(__fmul_rn(x2, p), -8.60467152213735e-11f);
    p = __fadd_rn(__fmul_rn(x2, p),  5.12229709037114e-08f);
    p = __fadd_rn(__fmul_rn(x2, p),  1.48572235717979e-05f);
    p = __fadd_rn(__fmul_rn(x2, p),  6.37261928875436e-04f);
    p = __fadd_rn(__fmul_rn(x2, p),  4.89352455891786e-03f);
    p = __fmul_rn(xc, p);
    float q;
    q = __fadd_rn(__fmul_rn(x2, 1.19825839466702e-06f), 1.18534705686654e-04f);
    q = __fadd_rn(__fmul_rn(x2, q), 2.26843463243900e-03f);
    q = __fadd_rn(__fmul_rn(x2, q), 4.89352518554385e-03f);
    float t = __fdiv_rn(p, q);
    return (ax < 0.0004f) ? x : t;
}
__device__ __forceinline__ float xla_sigmoid_f32(float x) {
    float t = xla_tanh_f32(__fmul_rn(x, 0.5f));
    return __fadd_rn(0.5f, __fmul_rn(0.5f, t));
}

// ---------------- cp.async --------------------------------------------------
__device__ __forceinline__ void cp16(void* dst_smem, const void* src) {
    uint32_t d = (uint32_t)__cvta_generic_to_shared(dst_smem);
    asm volatile("cp.async.cg.shared.global [%0], [%1], 16;\n" :: "r"(d), "l"(src));
}
__device__ __forceinline__ void cp_commit() { asm volatile("cp.async.commit_group;\n"); }
__device__ __forceinline__ void cp_wait1()  { asm volatile("cp.async.wait_group 1;\n"); }
__device__ __forceinline__ void cp_wait0()  { asm volatile("cp.async.wait_group 0;\n"); }

// ---------------- fp16 mma m16n8k16 ------------------------------------------
__device__ __forceinline__ void mma16816(float& d0, float& d1, float& d2, float& d3,
                                         uint32_t a0, uint32_t a1, uint32_t a2, uint32_t a3,
                                         uint32_t b0, uint32_t b1) {
    asm volatile(
        "mma.sync.aligned.m16n8k16.row.col.f32.f16.f16.f32 "
        "{%0,%1,%2,%3},{%4,%5,%6,%7},{%8,%9},{%0,%1,%2,%3};"
        : "+f"(d0), "+f"(d1), "+f"(d2), "+f"(d3)
        : "r"(a0), "r"(a1), "r"(a2), "r"(a3), "r"(b0), "r"(b1));
}

// ---------------- setup kernels ---------------------------------------------
__global__ void k_zero() { g_nflagS = 0; g_nflagO = 0; }

__global__ void k_keys() {
    int t = threadIdx.x;
    if (t < NT) {
        uint32_t a, b;
        threefry2x32(0u, 42u, 0u, (uint32_t)t, a, b);
        g_k0[t] = a; g_k1[t] = b;
    }
}

__global__ __launch_bounds__(256) void k_half(const float* __restrict__ W,
                                              __half* __restrict__ Hh, int n) {
    int i = blockIdx.x * blockDim.x + threadIdx.x;
    if (i >= n) return;
    Hh[i] = __float2half_rn(W[i]);
}

// ---------------- K1: stochastic input spikes -------------------------------
__global__ __launch_bounds__(256) void k_gen(const float* __restrict__ x) {
    int idx = blockIdx.x * blockDim.x + threadIdx.x;
    if (idx >= NB * NIN) return;
    int b = idx / NIN, j = idx - b * NIN;
    float p = xla_sigmoid_f32(x[idx]);
    uint32_t m = 0;
#pragma unroll
    for (int t = 0; t < NT; t++) {
        uint32_t a, bb;
        threefry2x32(g_k0[t], g_k1[t], 0u, (uint32_t)idx, a, bb);
        uint32_t bits = a ^ bb;
        float u = __uint_as_float((bits >> 9) | 0x3F800000u) - 1.0f;
        m |= (u < p) ? (1u << t) : 0u;
    }
    g_jmask[idx] = (uint16_t)m;
    const __half one = __float2half(1.0f);
    const __half zero = __float2half(0.0f);
#pragma unroll
    for (int t = 0; t < NT; t++)
        g_Pre[(size_t)(t * NB + b) * NIN + j] = ((m >> t) & 1u) ? one : zero;
}

// ---------------- fp16 tensor-core GEMM --------------------------------------
// C[m][n] = sum_k A[m][k]*B[n][k]; A row-major, B [n][k] row-major.
// CTA tile 128x128x32, 8 warps (2m x 4n), warp tile 64x32, mma m16n8k16.
#define GTK 32
#define ROWH 40   // halves per smem row (32 data + 8 pad)

__global__ __launch_bounds__(256)
void gemm_mma(const __half* __restrict__ A,
              const __half* __restrict__ B,
              float* __restrict__ C, int M, int N, int K) {
    __shared__ __half As[2][128][ROWH];
    __shared__ __half Bs[2][128][ROWH];

    const int tid  = threadIdx.x;
    const int m0   = blockIdx.y * 128;
    const int n0   = blockIdx.x * 128;
    const int warp = tid >> 5;
    const int lane = tid & 31;
    const int wm   = (warp & 1) * 64;
    const int wn   = (warp >> 1) * 32;
    const int r    = lane >> 2;
    const int c2   = (lane & 3) * 2;

    float acc[4][4][4];
#pragma unroll
    for (int mi = 0; mi < 4; mi++)
#pragma unroll
        for (int nj = 0; nj < 4; nj++)
#pragma unroll
            for (int q = 0; q < 4; q++) acc[mi][nj][q] = 0.0f;

    auto issue_slab = [&](int kb, int s) {
#pragma unroll
        for (int it = 0; it < 2; it++) {
            int idx = it * 256 + tid;          // 0..511
            int row = idx >> 2;
            int ch  = idx & 3;
            size_t go = (size_t)row * K + kb + ch * 8;
            cp16(&As[s][row][ch * 8], A + (size_t)m0 * K + go);
            cp16(&Bs[s][row][ch * 8], B + (size_t)n0 * K + go);
        }
        cp_commit();
    };

    const int nslab = K / GTK;
    issue_slab(0, 0);
    int s = 0;
    for (int sl = 0; sl < nslab; sl++) {
        if (sl + 1 < nslab) { issue_slab((sl + 1) * GTK, s ^ 1); cp_wait1(); }
        else                { cp_wait0(); }
        __syncthreads();

#pragma unroll
        for (int kc = 0; kc < 2; kc++) {
            const int kh = kc * 16;
            uint32_t af[4][4];
#pragma unroll
            for (int mi = 0; mi < 4; mi++) {
                const __half* base = &As[s][wm + 16 * mi][kh];
                af[mi][0] = *(const uint32_t*)&base[(size_t)(r)     * ROWH + c2];
                af[mi][1] = *(const uint32_t*)&base[(size_t)(r + 8) * ROWH + c2];
                af[mi][2] = *(const uint32_t*)&base[(size_t)(r)     * ROWH + c2 + 8];
                af[mi][3] = *(const uint32_t*)&base[(size_t)(r + 8) * ROWH + c2 + 8];
            }
            uint32_t bf[4][2];
#pragma unroll
            for (int nj = 0; nj < 4; nj++) {
                const __half* base = &Bs[s][wn + 8 * nj + r][kh];
                bf[nj][0] = *(const uint32_t*)&base[c2];
                bf[nj][1] = *(const uint32_t*)&base[c2 + 8];
            }
#pragma unroll
            for (int mi = 0; mi < 4; mi++)
#pragma unroll
                for (int nj = 0; nj < 4; nj++)
                    mma16816(acc[mi][nj][0], acc[mi][nj][1], acc[mi][nj][2], acc[mi][nj][3],
                             af[mi][0], af[mi][1], af[mi][2], af[mi][3],
                             bf[nj][0], bf[nj][1]);
        }
        __syncthreads();
        if (sl + 1 < nslab) s ^= 1;
    }

#pragma unroll
    for (int mi = 0; mi < 4; mi++)
#pragma unroll
        for (int nj = 0; nj < 4; nj++) {
            int row = m0 + wm + 16 * mi + r;
            int col = n0 + wn + 8 * nj + c2;
            *(float2*)&C[(size_t)row * N + col] =
                make_float2(acc[mi][nj][0], acc[mi][nj][1]);
            *(float2*)&C[(size_t)(row + 8) * N + col] =
                make_float2(acc[mi][nj][2], acc[mi][nj][3]);
        }
}

// ---------------- K3: LIF scan + flagging -----------------------------------
__global__ __launch_bounds__(256) void k_lif() {
    int i = blockIdx.x * blockDim.x + threadIdx.x;
    if (i >= NB * NHID) return;
    int b = i >> 11, h = i & (NHID - 1);
    float v = 0.0f;
    uint32_t m = 0;
    bool flag = false;
#pragma unroll
    for (int t = 0; t < NT; t++) {
        float hv = g_H[(size_t)(t * NB + b) * NHID + h];
        v = __fadd_rn(__fmul_rn(v, 0.3f), hv);
        flag |= fabsf(v - 1.0f) < MARGIN_V;
        if (v >= 1.0f) { m |= (1u << t); v = 0.0f; }
    }
    g_smask[i] = (uint16_t)m;
    const __half one = __float2half(1.0f);
    const __half zero = __float2half(0.0f);
#pragma unroll
    for (int t = 0; t < NT; t++)
        g_S[(size_t)(t * NB + b) * NHID + h] = ((m >> t) & 1u) ? one : zero;
    if (flag) {
        int pos = atomicAdd(&g_nflagS, 1);
        if (pos < CAPS) g_flagS[pos] = i;
    }
}

// exact recompute of flagged (b,h): all 10 h-sums in one pass (ref order),
// then exact v-chain, rewrite mask + S row.
__global__ __launch_bounds__(128) void k_fixS(const float* __restrict__ W_in) {
    int idx = blockIdx.x * blockDim.x + threadIdx.x;
    int n = g_nflagS; if (n > CAPS) n = CAPS;
    if (idx >= n) return;
    int i = g_flagS[idx];
    int b = i >> 11, h = i & (NHID - 1);
    const uint16_t* mrow = g_jmask + (size_t)b * NIN;
    const float* wrow = W_in + (size_t)h * NIN;
    float acc[NT];
#pragma unroll
    for (int t = 0; t < NT; t++) acc[t] = 0.0f;
    for (int j = 0; j < NIN; j++) {
        float w = wrow[j];
        uint32_t mk = mrow[j];
#pragma unroll
        for (int t = 0; t < NT; t++)
            acc[t] = __fadd_rn(acc[t], ((mk >> t) & 1u) ? w : 0.0f);
    }
    float v = 0.0f;
    uint32_t m = 0;
#pragma unroll
    for (int t = 0; t < NT; t++) {
        v = __fadd_rn(__fmul_rn(v, 0.3f), acc[t]);
        if (v >= 1.0f) { m |= (1u << t); v = 0.0f; }
    }
    g_smask[i] = (uint16_t)m;
    const __half one = __float2half(1.0f);
    const __half zero = __float2half(0.0f);
#pragma unroll
    for (int t = 0; t < NT; t++)
        g_S[(size_t)(t * NB + b) * NHID + h] = ((m >> t) & 1u) ? one : zero;
}

// ---------------- output flag + exact fix + count ---------------------------
__global__ __launch_bounds__(256) void k_flagO(const float* __restrict__ b_out) {
    int i = blockIdx.x * blockDim.x + threadIdx.x;
    if (i >= NM * NOUT) return;
    float val = __fadd_rn(g_O[i], b_out[i & (NOUT - 1)]);
    if (fabsf(val) < MARGIN_O) {
        int pos = atomicAdd(&g_nflagO, 1);
        if (pos < CAPO) g_flagO[pos] = i;
    }
}

__global__ __launch_bounds__(256) void k_fixO(const float* __restrict__ W_out) {
    int idx = blockIdx.x * blockDim.x + threadIdx.x;
    int n = g_nflagO; if (n > CAPO) n = CAPO;
    if (idx >= n) return;
    int i = g_flagO[idx];
    int m = i / NOUT, o = i - m * NOUT;
    int b = m & (NB - 1), t = m / NB;
    const uint16_t* srow = g_smask + (size_t)b * NHID;
    const float* wrow = W_out + (size_t)o * NHID;
    float acc = 0.0f;
    for (int h = 0; h < NHID; h++) {
        float w = wrow[h];
        acc = __fadd_rn(acc, ((srow[h] >> t) & 1u) ? w : 0.0f);
    }
    g_O[i] = acc;
}

__global__ __launch_bounds__(256) void k_count(const float* __restrict__ b_out,
                                               float* __restrict__ out) {
    int i = blockIdx.x * blockDim.x + threadIdx.x;
    if (i >= NB * NOUT) return;
    float bo = b_out[i & (NOUT - 1)];
    float s = 0.0f;
#pragma unroll
    for (int t = 0; t < NT; t++) {
        float val = __fadd_rn(g_O[(size_t)t * (NB * NOUT) + i], bo);
        s += (val > 0.0f) ? 1.0f : 0.0f;
    }
    out[i] = s;
}

// ---------------- launch ----------------------------------------------------
extern "C" void kernel_launch(void* const* d_in, const int* in_sizes, int n_in,
                              void* d_out, int out_size) {
    const float* x     = (const float*)d_in[0];
    const float* W_in  = (const float*)d_in[1];
    const float* W_out = (const float*)d_in[2];
    const float* b_out = (const float*)d_in[3];
    float* out = (float*)d_out;

    void *p_Pre, *p_S, *p_WiH, *p_WoH, *p_H, *p_O;
    cudaGetSymbolAddress(&p_Pre, g_Pre);
    cudaGetSymbolAddress(&p_S,   g_S);
    cudaGetSymbolAddress(&p_WiH, g_WinH);
    cudaGetSymbolAddress(&p_WoH, g_WoutH);
    cudaGetSymbolAddress(&p_H,   g_H);
    cudaGetSymbolAddress(&p_O,   g_O);

    k_zero<<<1, 1>>>();
    k_keys<<<1, 32>>>();
    k_half<<<(NHID * NIN + 255) / 256, 256>>>(W_in,  (__half*)p_WiH, NHID * NIN);
    k_half<<<(NOUT * NHID + 255) / 256, 256>>>(W_out, (__half*)p_WoH, NOUT * NHID);
    k_gen<<<(NB * NIN + 255) / 256, 256>>>(x);

    {   // H = PRE @ W_in^T
        dim3 grid(NHID / 128, NM / 128);
        gemm_mma<<<grid, 256>>>((const __half*)p_Pre, (const __half*)p_WiH,
                                (float*)p_H, NM, NHID, NIN);
    }

    k_lif<<<(NB * NHID + 255) / 256, 256>>>();
    k_fixS<<<(CAPS + 127) / 128, 128>>>(W_in);

    {   // O = S @ W_out^T
        dim3 grid(NOUT / 128, NM / 128);
        gemm_mma<<<grid, 256>>>((const __half*)p_S, (const __half*)p_WoH,
                                (float*)p_O, NM, NOUT, NHID);
    }

    k_flagO<<<(NM * NOUT + 255) / 256, 256>>>(b_out);
    k_fixO<<<(CAPO + 255) / 256, 256>>>(W_out);
    k_count<<<(NB * NOUT + 255) / 256, 256>>>(b_out, out);
}

// round 8
// speedup vs baseline: 1.0012x; 1.0012x over previous
#include <cuda_runtime.h>
#include <cuda_bf16.h>
#include <cstdint>

// ============================================================================
// SpikingNetwork, T=10. B=512, input=3072, hidden=2048, out=512
// R4 architecture (proven 1339us, rel_err 0.0): 2-limb bf16 mma.sync GEMMs +
// margin flagging + exact fp32 recompute of flagged elements.
// R7: dynamic smem for the 3-stage pipeline (static smem exceeded 48KB cap);
// launch order keeps gemm1 at position #4 for ncu capture.
// ============================================================================

#define NB   512
#define NIN  3072
#define NHID 2048
#define NOUT 512
#define NT   10
#define NM   (NT * NB)     // 5120

#define MARGIN_V 3e-4f
#define MARGIN_O 1e-4f
#define CAPS 65536
#define CAPO 65536

__device__ __align__(16) __nv_bfloat16 g_Pre [NM * NIN];
__device__ __align__(16) __nv_bfloat16 g_S   [NM * NHID];
__device__ __align__(16) __nv_bfloat16 g_WinHi [NHID * NIN];
__device__ __align__(16) __nv_bfloat16 g_WinMid[NHID * NIN];
__device__ __align__(16) __nv_bfloat16 g_WoutHi [NOUT * NHID];
__device__ __align__(16) __nv_bfloat16 g_WoutMid[NOUT * NHID];
__device__ float    g_H[NM * NHID];
__device__ float    g_O[NM * NOUT];
__device__ uint16_t g_jmask[NB * NIN];
__device__ uint16_t g_smask[NB * NHID];
__device__ uint32_t g_k0[NT];
__device__ uint32_t g_k1[NT];
__device__ int      g_nflagS;
__device__ int      g_flagS[CAPS];
__device__ int      g_nflagO;
__device__ int      g_flagO[CAPO];

// ---------------- threefry2x32 (JAX-exact, 20 rounds) -----------------------
__device__ __forceinline__ uint32_t rotl32(uint32_t x, int r) {
    return __funnelshift_l(x, x, r);
}
__device__ __forceinline__ void threefry2x32(uint32_t k0, uint32_t k1,
                                             uint32_t x0, uint32_t x1,
                                             uint32_t& o0, uint32_t& o1) {
    uint32_t ks2 = k0 ^ k1 ^ 0x1BD11BDAu;
    x0 += k0; x1 += k1;
#define TF_R(r) { x0 += x1; x1 = rotl32(x1, (r)); x1 ^= x0; }
    TF_R(13) TF_R(15) TF_R(26) TF_R(6)
    x0 += k1;  x1 += ks2 + 1u;
    TF_R(17) TF_R(29) TF_R(16) TF_R(24)
    x0 += ks2; x1 += k0 + 2u;
    TF_R(13) TF_R(15) TF_R(26) TF_R(6)
    x0 += k0;  x1 += k1 + 3u;
    TF_R(17) TF_R(29) TF_R(16) TF_R(24)
    x0 += k1;  x1 += ks2 + 4u;
    TF_R(13) TF_R(15) TF_R(26) TF_R(6)
    x0 += ks2; x1 += k0 + 5u;
#undef TF_R
    o0 = x0; o1 = x1;
}

// ---------------- XLA logistic ----------------------------------------------
__device__ __forceinline__ float xla_tanh_f32(float x) {
    const float kClamp = 7.90531110763549805f;
    float ax = fabsf(x);
    float xc = fminf(fmaxf(x, -kClamp), kClamp);
    float x2 = __fmul_rn(xc, xc);
    float p;
    p = __fadd_rn(__fmul_rn(x2, -2.76076847742355e-16f), 2.00018790482477e-13f);
    p = __fadd_rn(__fmul_rn(x2, p), -8.60467152213735e-11f);
    p = __fadd_rn(__fmul_rn(x2, p),  5.12229709037114e-08f);
    p = __fadd_rn(__fmul_rn(x2, p),  1.48572235717979e-05f);
    p = __fadd_rn(__fmul_rn(x2, p),  6.37261928875436e-04f);
    p = __fadd_rn(__fmul_rn(x2, p),  4.89352455891786e-03f);
    p = __fmul_rn(xc, p);
    float q;
    q = __fadd_rn(__fmul_rn(x2, 1.19825839466702e-06f), 1.18534705686654e-04f);
    q = __fadd_rn(__fmul_rn(x2, q), 2.26843463243900e-03f);
    q = __fadd_rn(__fmul_rn(x2, q), 4.89352518554385e-03f);
    float t = __fdiv_rn(p, q);
    return (ax < 0.0004f) ? x : t;
}
__device__ __forceinline__ float xla_sigmoid_f32(float x) {
    float t = xla_tanh_f32(__fmul_rn(x, 0.5f));
    return __fadd_rn(0.5f, __fmul_rn(0.5f, t));
}

// ---------------- cp.async --------------------------------------------------
__device__ __forceinline__ void cp16(void* dst_smem, const void* src) {
    uint32_t d = (uint32_t)__cvta_generic_to_shared(dst_smem);
    asm volatile("cp.async.cg.shared.global [%0], [%1], 16;\n" :: "r"(d), "l"(src));
}
__device__ __forceinline__ void cp_commit() { asm volatile("cp.async.commit_group;\n"); }
__device__ __forceinline__ void cp_wait2()  { asm volatile("cp.async.wait_group 2;\n"); }
__device__ __forceinline__ void cp_wait1()  { asm volatile("cp.async.wait_group 1;\n"); }
__device__ __forceinline__ void cp_wait0()  { asm volatile("cp.async.wait_group 0;\n"); }

// ---------------- bf16 mma m16n8k16 -----------------------------------------
__device__ __forceinline__ void mma16816(float& d0, float& d1, float& d2, float& d3,
                                         uint32_t a0, uint32_t a1, uint32_t a2, uint32_t a3,
                                         uint32_t b0, uint32_t b1) {
    asm volatile(
        "mma.sync.aligned.m16n8k16.row.col.f32.bf16.bf16.f32 "
        "{%0,%1,%2,%3},{%4,%5,%6,%7},{%8,%9},{%0,%1,%2,%3};"
        : "+f"(d0), "+f"(d1), "+f"(d2), "+f"(d3)
        : "r"(a0), "r"(a1), "r"(a2), "r"(a3), "r"(b0), "r"(b1));
}

// ---------------- setup: keys + flag counters (launch #1) -------------------
__global__ void k_setup() {
    int t = threadIdx.x;
    if (t == 0) { g_nflagS = 0; g_nflagO = 0; }
    if (t < NT) {
        uint32_t a, b;
        threefry2x32(0u, 42u, 0u, (uint32_t)t, a, b);
        g_k0[t] = a; g_k1[t] = b;
    }
}

// both weight limb splits in one kernel (launch #2)
__global__ __launch_bounds__(256) void k_limbs2(const float* __restrict__ Wi,
                                                const float* __restrict__ Wo) {
    int i = blockIdx.x * blockDim.x + threadIdx.x;
    const int n1 = NHID * NIN;
    const int n2 = NOUT * NHID;
    if (i >= n1 + n2) return;
    const float* W = (i < n1) ? Wi : Wo;
    __nv_bfloat16* Hi  = (i < n1) ? g_WinHi  : g_WoutHi;
    __nv_bfloat16* Mid = (i < n1) ? g_WinMid : g_WoutMid;
    int k = (i < n1) ? i : i - n1;
    float w = W[k];
    __nv_bfloat16 h = __float2bfloat16(w);
    float r = __fadd_rn(w, -__bfloat162float(h));
    Hi[k] = h;
    Mid[k] = __float2bfloat16(r);
}

// ---------------- K1: stochastic input spikes (launch #3) -------------------
__global__ __launch_bounds__(256) void k_gen(const float* __restrict__ x) {
    int idx = blockIdx.x * blockDim.x + threadIdx.x;
    if (idx >= NB * NIN) return;
    int b = idx / NIN, j = idx - b * NIN;
    float p = xla_sigmoid_f32(x[idx]);
    uint32_t m = 0;
#pragma unroll
    for (int t = 0; t < NT; t++) {
        uint32_t a, bb;
        threefry2x32(g_k0[t], g_k1[t], 0u, (uint32_t)idx, a, bb);
        uint32_t bits = a ^ bb;
        float u = __uint_as_float((bits >> 9) | 0x3F800000u) - 1.0f;
        m |= (u < p) ? (1u << t) : 0u;
    }
    g_jmask[idx] = (uint16_t)m;
    const __nv_bfloat16 one = __float2bfloat16(1.0f);
    const __nv_bfloat16 zero = __float2bfloat16(0.0f);
#pragma unroll
    for (int t = 0; t < NT; t++)
        g_Pre[(size_t)(t * NB + b) * NIN + j] = ((m >> t) & 1u) ? one : zero;
}

// ---------------- bf16 2-limb tensor-core GEMM (launch #4) ------------------
// C[m][n] = sum_k A[m][k]*(BH[n][k]+BM[n][k]); CTA 128x128x32, 8 warps,
// warp tile 64x32, mma m16n8k16, 3-stage cp.async pipeline, dynamic smem.
#define GTK 32
#define ROWH 40
#define NSTG 3
#define TILE_ELN (128 * ROWH)             // halves per tile
#define STAGE_ELN (3 * TILE_ELN)          // A + BH + BM per stage
#define SMEM_BYTES (NSTG * STAGE_ELN * 2) // 92160

__global__ __launch_bounds__(256)
void gemm_mma(const __nv_bfloat16* __restrict__ A,
              const __nv_bfloat16* __restrict__ BH,
              const __nv_bfloat16* __restrict__ BM,
              float* __restrict__ C, int M, int N, int K) {
    extern __shared__ __nv_bfloat16 smem[];
    // stage s: As = smem + s*STAGE_ELN, BsH = +TILE_ELN, BsM = +2*TILE_ELN

    const int tid  = threadIdx.x;
    const int m0   = blockIdx.y * 128;
    const int n0   = blockIdx.x * 128;
    const int warp = tid >> 5;
    const int lane = tid & 31;
    const int wm   = (warp & 1) * 64;
    const int wn   = (warp >> 1) * 32;
    const int r    = lane >> 2;
    const int c2   = (lane & 3) * 2;

    float acc[4][4][4];
#pragma unroll
    for (int mi = 0; mi < 4; mi++)
#pragma unroll
        for (int nj = 0; nj < 4; nj++)
#pragma unroll
            for (int q = 0; q < 4; q++) acc[mi][nj][q] = 0.0f;

    auto issue_slab = [&](int kb, int s) {
        __nv_bfloat16* st = smem + s * STAGE_ELN;
#pragma unroll
        for (int it = 0; it < 2; it++) {
            int idx = it * 256 + tid;
            int row = idx >> 2;
            int ch  = idx & 3;
            size_t go = (size_t)row * K + kb + ch * 8;
            int so = row * ROWH + ch * 8;
            cp16(st + so,                A  + (size_t)m0 * K + go);
            cp16(st + TILE_ELN + so,     BH + (size_t)n0 * K + go);
            cp16(st + 2 * TILE_ELN + so, BM + (size_t)n0 * K + go);
        }
        cp_commit();
    };

    const int nslab = K / GTK;
    issue_slab(0, 0);
    if (nslab > 1) issue_slab(GTK, 1);

    for (int sl = 0; sl < nslab; sl++) {
        const int s = sl % NSTG;
        if (sl + 2 < nslab) { issue_slab((sl + 2) * GTK, (sl + 2) % NSTG); cp_wait2(); }
        else if (sl + 1 < nslab) { cp_wait1(); }
        else { cp_wait0(); }
        __syncthreads();

        const __nv_bfloat16* As  = smem + s * STAGE_ELN;
        const __nv_bfloat16* BsH = As + TILE_ELN;
        const __nv_bfloat16* BsM = As + 2 * TILE_ELN;

#pragma unroll
        for (int kc = 0; kc < 2; kc++) {
            const int kh = kc * 16;
            uint32_t af[4][4];
#pragma unroll
            for (int mi = 0; mi < 4; mi++) {
                const __nv_bfloat16* base = As + (wm + 16 * mi) * ROWH + kh;
                af[mi][0] = *(const uint32_t*)&base[(r)     * ROWH + c2];
                af[mi][1] = *(const uint32_t*)&base[(r + 8) * ROWH + c2];
                af[mi][2] = *(const uint32_t*)&base[(r)     * ROWH + c2 + 8];
                af[mi][3] = *(const uint32_t*)&base[(r + 8) * ROWH + c2 + 8];
            }
            uint32_t bf[4][2];
#pragma unroll
            for (int nj = 0; nj < 4; nj++) {
                const __nv_bfloat16* base = BsH + (wn + 8 * nj + r) * ROWH + kh;
                bf[nj][0] = *(const uint32_t*)&base[c2];
                bf[nj][1] = *(const uint32_t*)&base[c2 + 8];
            }
#pragma unroll
            for (int mi = 0; mi < 4; mi++)
#pragma unroll
                for (int nj = 0; nj < 4; nj++)
                    mma16816(acc[mi][nj][0], acc[mi][nj][1], acc[mi][nj][2], acc[mi][nj][3],
                             af[mi][0], af[mi][1], af[mi][2], af[mi][3],
                             bf[nj][0], bf[nj][1]);
#pragma unroll
            for (int nj = 0; nj < 4; nj++) {
                const __nv_bfloat16* base = BsM + (wn + 8 * nj + r) * ROWH + kh;
                bf[nj][0] = *(const uint32_t*)&base[c2];
                bf[nj][1] = *(const uint32_t*)&base[c2 + 8];
            }
#pragma unroll
            for (int mi = 0; mi < 4; mi++)
#pragma unroll
                for (int nj = 0; nj < 4; nj++)
                    mma16816(acc[mi][nj][0], acc[mi][nj][1], acc[mi][nj][2], acc[mi][nj][3],
                             af[mi][0], af[mi][1], af[mi][2], af[mi][3],
                             bf[nj][0], bf[nj][1]);
        }
        __syncthreads();
    }

#pragma unroll
    for (int mi = 0; mi < 4; mi++)
#pragma unroll
        for (int nj = 0; nj < 4; nj++) {
            int row = m0 + wm + 16 * mi + r;
            int col = n0 + wn + 8 * nj + c2;
            *(float2*)&C[(size_t)row * N + col] =
                make_float2(acc[mi][nj][0], acc[mi][nj][1]);
            *(float2*)&C[(size_t)(row + 8) * N + col] =
                make_float2(acc[mi][nj][2], acc[mi][nj][3]);
        }
}

// ---------------- K3: LIF scan + flagging -----------------------------------
__global__ __launch_bounds__(256) void k_lif() {
    int i = blockIdx.x * blockDim.x + threadIdx.x;
    if (i >= NB * NHID) return;
    int b = i >> 11, h = i & (NHID - 1);
    float v = 0.0f;
    uint32_t m = 0;
    bool flag = false;
#pragma unroll
    for (int t = 0; t < NT; t++) {
        float hv = g_H[(size_t)(t * NB + b) * NHID + h];
        v = __fadd_rn(__fmul_rn(v, 0.3f), hv);
        flag |= fabsf(v - 1.0f) < MARGIN_V;
        if (v >= 1.0f) { m |= (1u << t); v = 0.0f; }
    }
    g_smask[i] = (uint16_t)m;
    const __nv_bfloat16 one = __float2bfloat16(1.0f);
    const __nv_bfloat16 zero = __float2bfloat16(0.0f);
#pragma unroll
    for (int t = 0; t < NT; t++)
        g_S[(size_t)(t * NB + b) * NHID + h] = ((m >> t) & 1u) ? one : zero;
    if (flag) {
        int pos = atomicAdd(&g_nflagS, 1);
        if (pos < CAPS) g_flagS[pos] = i;
    }
}

// one-pass exact recompute of flagged (b,h)
__global__ __launch_bounds__(128) void k_fixS(const float* __restrict__ W_in) {
    int idx = blockIdx.x * blockDim.x + threadIdx.x;
    int n = g_nflagS; if (n > CAPS) n = CAPS;
    if (idx >= n) return;
    int i = g_flagS[idx];
    int b = i >> 11, h = i & (NHID - 1);
    const uint16_t* mrow = g_jmask + (size_t)b * NIN;
    const float* wrow = W_in + (size_t)h * NIN;
    float acc[NT];
#pragma unroll
    for (int t = 0; t < NT; t++) acc[t] = 0.0f;
    for (int j = 0; j < NIN; j++) {
        float w = wrow[j];
        uint32_t mk = mrow[j];
#pragma unroll
        for (int t = 0; t < NT; t++)
            acc[t] = __fadd_rn(acc[t], ((mk >> t) & 1u) ? w : 0.0f);
    }
    float v = 0.0f;
    uint32_t m = 0;
#pragma unroll
    for (int t = 0; t < NT; t++) {
        v = __fadd_rn(__fmul_rn(v, 0.3f), acc[t]);
        if (v >= 1.0f) { m |= (1u << t); v = 0.0f; }
    }
    g_smask[i] = (uint16_t)m;
    const __nv_bfloat16 one = __float2bfloat16(1.0f);
    const __nv_bfloat16 zero = __float2bfloat16(0.0f);
#pragma unroll
    for (int t = 0; t < NT; t++)
        g_S[(size_t)(t * NB + b) * NHID + h] = ((m >> t) & 1u) ? one : zero;
}

// ---------------- output flag + exact fix + count ---------------------------
__global__ __launch_bounds__(256) void k_flagO(const float* __restrict__ b_out) {
    int i = blockIdx.x * blockDim.x + threadIdx.x;
    if (i >= NM * NOUT) return;
    float val = __fadd_rn(g_O[i], b_out[i & (NOUT - 1)]);
    if (fabsf(val) < MARGIN_O) {
        int pos = atomicAdd(&g_nflagO, 1);
        if (pos < CAPO) g_flagO[pos] = i;
    }
}

__global__ __launch_bounds__(256) void k_fixO(const float* __restrict__ W_out) {
    int idx = blockIdx.x * blockDim.x + threadIdx.x;
    int n = g_nflagO; if (n > CAPO) n = CAPO;
    if (idx >= n) return;
    int i = g_flagO[idx];
    int m = i / NOUT, o = i - m * NOUT;
    int b = m & (NB - 1), t = m / NB;
    const uint16_t* srow = g_smask + (size_t)b * NHID;
    const float* wrow = W_out + (size_t)o * NHID;
    float acc = 0.0f;
    for (int h = 0; h < NHID; h++) {
        float w = wrow[h];
        acc = __fadd_rn(acc, ((srow[h] >> t) & 1u) ? w : 0.0f);
    }
    g_O[i] = acc;
}

__global__ __launch_bounds__(256) void k_count(const float* __restrict__ b_out,
                                               float* __restrict__ out) {
    int i = blockIdx.x * blockDim.x + threadIdx.x;
    if (i >= NB * NOUT) return;
    float bo = b_out[i & (NOUT - 1)];
    float s = 0.0f;
#pragma unroll
    for (int t = 0; t < NT; t++) {
        float val = __fadd_rn(g_O[(size_t)t * (NB * NOUT) + i], bo);
        s += (val > 0.0f) ? 1.0f : 0.0f;
    }
    out[i] = s;
}

// ---------------- launch ----------------------------------------------------
extern "C" void kernel_launch(void* const* d_in, const int* in_sizes, int n_in,
                              void* d_out, int out_size) {
    const float* x     = (const float*)d_in[0];
    const float* W_in  = (const float*)d_in[1];
    const float* W_out = (const float*)d_in[2];
    const float* b_out = (const float*)d_in[3];
    float* out = (float*)d_out;

    static bool attr_set = false;
    if (!attr_set) {
        cudaFuncSetAttribute(gemm_mma, cudaFuncAttributeMaxDynamicSharedMemorySize,
                             SMEM_BYTES);
        attr_set = true;
    }

    void *p_Pre, *p_S, *p_WiH, *p_WiM, *p_WoH, *p_WoM, *p_H, *p_O;
    cudaGetSymbolAddress(&p_Pre, g_Pre);
    cudaGetSymbolAddress(&p_S,   g_S);
    cudaGetSymbolAddress(&p_WiH, g_WinHi);
    cudaGetSymbolAddress(&p_WiM, g_WinMid);
    cudaGetSymbolAddress(&p_WoH, g_WoutHi);
    cudaGetSymbolAddress(&p_WoM, g_WoutMid);
    cudaGetSymbolAddress(&p_H,   g_H);
    cudaGetSymbolAddress(&p_O,   g_O);

    k_setup<<<1, 32>>>();                                            // #1
    k_limbs2<<<(NHID * NIN + NOUT * NHID + 255) / 256, 256>>>(W_in, W_out); // #2
    k_gen<<<(NB * NIN + 255) / 256, 256>>>(x);                       // #3

    {   // #4 (ncu-captured): H = PRE @ W_in^T
        dim3 grid(NHID / 128, NM / 128);
        gemm_mma<<<grid, 256, SMEM_BYTES>>>((const __nv_bfloat16*)p_Pre,
            (const __nv_bfloat16*)p_WiH, (const __nv_bfloat16*)p_WiM,
            (float*)p_H, NM, NHID, NIN);
    }

    k_lif<<<(NB * NHID + 255) / 256, 256>>>();                       // #5
    k_fixS<<<(CAPS + 127) / 128, 128>>>(W_in);                       // #6

    {   // #7: O = S @ W_out^T
        dim3 grid(NOUT / 128, NM / 128);
        gemm_mma<<<grid, 256, SMEM_BYTES>>>((const __nv_bfloat16*)p_S,
            (const __nv_bfloat16*)p_WoH, (const __nv_bfloat16*)p_WoM,
            (float*)p_O, NM, NOUT, NHID);
    }

    k_flagO<<<(NM * NOUT + 255) / 256, 256>>>(b_out);                // #8
    k_fixO<<<(CAPO + 255) / 256, 256>>>(W_out);                      // #9
    k_count<<<(NB * NOUT + 255) / 256, 256>>>(b_out, out);           // #10
}

// round 9
// speedup vs baseline: 1.0087x; 1.0075x over previous
#include <cuda_runtime.h>
#include <cuda_bf16.h>
#include <cstdint>

// ============================================================================
// SpikingNetwork, T=10. B=512, input=3072, hidden=2048, out=512
// 2-limb bf16 mma.sync GEMMs + margin flagging + exact fp32 recompute.
// R9: revert to proven 2-stage pipeline (R4); fragment loads via ldmatrix.x4
// (was 32x LDS.32 per k16-step -> 8x LDSM) to unstall the tensor pipe
// (ncu R8: tensor=50.6%, DRAM=2%, L1=30.5% -> shared-issue bound).
// ============================================================================

#define NB   512
#define NIN  3072
#define NHID 2048
#define NOUT 512
#define NT   10
#define NM   (NT * NB)     // 5120

#define MARGIN_V 3e-4f
#define MARGIN_O 1e-4f
#define CAPS 65536
#define CAPO 65536

__device__ __align__(16) __nv_bfloat16 g_Pre [NM * NIN];
__device__ __align__(16) __nv_bfloat16 g_S   [NM * NHID];
__device__ __align__(16) __nv_bfloat16 g_WinHi [NHID * NIN];
__device__ __align__(16) __nv_bfloat16 g_WinMid[NHID * NIN];
__device__ __align__(16) __nv_bfloat16 g_WoutHi [NOUT * NHID];
__device__ __align__(16) __nv_bfloat16 g_WoutMid[NOUT * NHID];
__device__ float    g_H[NM * NHID];
__device__ float    g_O[NM * NOUT];
__device__ uint16_t g_jmask[NB * NIN];
__device__ uint16_t g_smask[NB * NHID];
__device__ uint32_t g_k0[NT];
__device__ uint32_t g_k1[NT];
__device__ int      g_nflagS;
__device__ int      g_flagS[CAPS];
__device__ int      g_nflagO;
__device__ int      g_flagO[CAPO];

// ---------------- threefry2x32 (JAX-exact, 20 rounds) -----------------------
__device__ __forceinline__ uint32_t rotl32(uint32_t x, int r) {
    return __funnelshift_l(x, x, r);
}
__device__ __forceinline__ void threefry2x32(uint32_t k0, uint32_t k1,
                                             uint32_t x0, uint32_t x1,
                                             uint32_t& o0, uint32_t& o1) {
    uint32_t ks2 = k0 ^ k1 ^ 0x1BD11BDAu;
    x0 += k0; x1 += k1;
#define TF_R(r) { x0 += x1; x1 = rotl32(x1, (r)); x1 ^= x0; }
    TF_R(13) TF_R(15) TF_R(26) TF_R(6)
    x0 += k1;  x1 += ks2 + 1u;
    TF_R(17) TF_R(29) TF_R(16) TF_R(24)
    x0 += ks2; x1 += k0 + 2u;
    TF_R(13) TF_R(15) TF_R(26) TF_R(6)
    x0 += k0;  x1 += k1 + 3u;
    TF_R(17) TF_R(29) TF_R(16) TF_R(24)
    x0 += k1;  x1 += ks2 + 4u;
    TF_R(13) TF_R(15) TF_R(26) TF_R(6)
    x0 += ks2; x1 += k0 + 5u;
#undef TF_R
    o0 = x0; o1 = x1;
}

// ---------------- XLA logistic ----------------------------------------------
__device__ __forceinline__ float xla_tanh_f32(float x) {
    const float kClamp = 7.90531110763549805f;
    float ax = fabsf(x);
    float xc = fminf(fmaxf(x, -kClamp), kClamp);
    float x2 = __fmul_rn(xc, xc);
    float p;
    p = __fadd_rn(__fmul_rn(x2, -2.76076847742355e-16f), 2.00018790482477e-13f);
    p = __fadd_rn(__fmul_rn(x2, p), -8.60467152213735e-11f);
    p = __fadd_rn(__fmul_rn(x2, p),  5.12229709037114e-08f);
    p = __fadd_rn(__fmul_rn(x2, p),  1.48572235717979e-05f);
    p = __fadd_rn(__fmul_rn(x2, p),  6.37261928875436e-04f);
    p = __fadd_rn(__fmul_rn(x2, p),  4.89352455891786e-03f);
    p = __fmul_rn(xc, p);
    float q;
    q = __fadd_rn(__fmul_rn(x2, 1.19825839466702e-06f), 1.18534705686654e-04f);
    q = __fadd_rn(__fmul_rn(x2, q), 2.26843463243900e-03f);
    q = __fadd_rn(__fmul_rn(x2, q), 4.89352518554385e-03f);
    float t = __fdiv_rn(p, q);
    return (ax < 0.0004f) ? x : t;
}
__device__ __forceinline__ float xla_sigmoid_f32(float x) {
    float t = xla_tanh_f32(__fmul_rn(x, 0.5f));
    return __fadd_rn(0.5f, __fmul_rn(0.5f, t));
}

// ---------------- cp.async / ldmatrix ---------------------------------------
__device__ __forceinline__ void cp16(void* dst_smem, const void* src) {
    uint32_t d = (uint32_t)__cvta_generic_to_shared(dst_smem);
    asm volatile("cp.async.cg.shared.global [%0], [%1], 16;\n" :: "r"(d), "l"(src));
}
__device__ __forceinline__ void cp_commit() { asm volatile("cp.async.commit_group;\n"); }
__device__ __forceinline__ void cp_wait1()  { asm volatile("cp.async.wait_group 1;\n"); }
__device__ __forceinline__ void cp_wait0()  { asm volatile("cp.async.wait_group 0;\n"); }

__device__ __forceinline__ void ldsm_x4(uint32_t& r0, uint32_t& r1,
                                        uint32_t& r2, uint32_t& r3, uint32_t addr) {
    asm volatile("ldmatrix.sync.aligned.m8n8.x4.shared.b16 {%0,%1,%2,%3}, [%4];"
                 : "=r"(r0), "=r"(r1), "=r"(r2), "=r"(r3) : "r"(addr));
}

// ---------------- bf16 mma m16n8k16 -----------------------------------------
__device__ __forceinline__ void mma16816(float& d0, float& d1, float& d2, float& d3,
                                         uint32_t a0, uint32_t a1, uint32_t a2, uint32_t a3,
                                         uint32_t b0, uint32_t b1) {
    asm volatile(
        "mma.sync.aligned.m16n8k16.row.col.f32.bf16.bf16.f32 "
        "{%0,%1,%2,%3},{%4,%5,%6,%7},{%8,%9},{%0,%1,%2,%3};"
        : "+f"(d0), "+f"(d1), "+f"(d2), "+f"(d3)
        : "r"(a0), "r"(a1), "r"(a2), "r"(a3), "r"(b0), "r"(b1));
}

// ---------------- setup (launch #1) -----------------------------------------
__global__ void k_setup() {
    int t = threadIdx.x;
    if (t == 0) { g_nflagS = 0; g_nflagO = 0; }
    if (t < NT) {
        uint32_t a, b;
        threefry2x32(0u, 42u, 0u, (uint32_t)t, a, b);
        g_k0[t] = a; g_k1[t] = b;
    }
}

// weight limb splits (launch #2)
__global__ __launch_bounds__(256) void k_limbs2(const float* __restrict__ Wi,
                                                const float* __restrict__ Wo) {
    int i = blockIdx.x * blockDim.x + threadIdx.x;
    const int n1 = NHID * NIN;
    const int n2 = NOUT * NHID;
    if (i >= n1 + n2) return;
    const float* W = (i < n1) ? Wi : Wo;
    __nv_bfloat16* Hi  = (i < n1) ? g_WinHi  : g_WoutHi;
    __nv_bfloat16* Mid = (i < n1) ? g_WinMid : g_WoutMid;
    int k = (i < n1) ? i : i - n1;
    float w = W[k];
    __nv_bfloat16 h = __float2bfloat16(w);
    float r = __fadd_rn(w, -__bfloat162float(h));
    Hi[k] = h;
    Mid[k] = __float2bfloat16(r);
}

// ---------------- K1: stochastic input spikes (launch #3) -------------------
__global__ __launch_bounds__(256) void k_gen(const float* __restrict__ x) {
    int idx = blockIdx.x * blockDim.x + threadIdx.x;
    if (idx >= NB * NIN) return;
    int b = idx / NIN, j = idx - b * NIN;
    float p = xla_sigmoid_f32(x[idx]);
    uint32_t m = 0;
#pragma unroll
    for (int t = 0; t < NT; t++) {
        uint32_t a, bb;
        threefry2x32(g_k0[t], g_k1[t], 0u, (uint32_t)idx, a, bb);
        uint32_t bits = a ^ bb;
        float u = __uint_as_float((bits >> 9) | 0x3F800000u) - 1.0f;
        m |= (u < p) ? (1u << t) : 0u;
    }
    g_jmask[idx] = (uint16_t)m;
    const __nv_bfloat16 one = __float2bfloat16(1.0f);
    const __nv_bfloat16 zero = __float2bfloat16(0.0f);
#pragma unroll
    for (int t = 0; t < NT; t++)
        g_Pre[(size_t)(t * NB + b) * NIN + j] = ((m >> t) & 1u) ? one : zero;
}

// ---------------- bf16 2-limb tensor-core GEMM (launch #4) ------------------
// C[m][n] = sum_k A[m][k]*(BH[n][k]+BM[n][k]); CTA 128x128x32, 8 warps,
// warp tile 64x32, m16n8k16, 2-stage cp.async pipeline, ldmatrix fragments.
#define GTK 32
#define ROWH 40                             // halves per smem row (80B stride)
#define NSTG 2
#define TILE_ELN (128 * ROWH)
#define STAGE_ELN (3 * TILE_ELN)
#define SMEM_BYTES (NSTG * STAGE_ELN * 2)   // 61440

__global__ __launch_bounds__(256)
void gemm_mma(const __nv_bfloat16* __restrict__ A,
              const __nv_bfloat16* __restrict__ BH,
              const __nv_bfloat16* __restrict__ BM,
              float* __restrict__ C, int M, int N, int K) {
    extern __shared__ __nv_bfloat16 smem[];

    const int tid  = threadIdx.x;
    const int m0   = blockIdx.y * 128;
    const int n0   = blockIdx.x * 128;
    const int warp = tid >> 5;
    const int lane = tid & 31;
    const int wm   = (warp & 1) * 64;
    const int wn   = (warp >> 1) * 32;
    const int r    = lane >> 2;
    const int c2   = (lane & 3) * 2;

    // ldmatrix per-lane address components (byte offsets within a tile)
    const uint32_t sbase = (uint32_t)__cvta_generic_to_shared(smem);
    const uint32_t aLane = (uint32_t)(((wm + (lane & 15)) * ROWH + ((lane >> 4) * 8)) * 2);
    const uint32_t bLane = (uint32_t)(((wn + 8 * (lane >> 4) + (lane & 7)) * ROWH
                                       + (((lane >> 3) & 1) * 8)) * 2);

    float acc[4][4][4];
#pragma unroll
    for (int mi = 0; mi < 4; mi++)
#pragma unroll
        for (int nj = 0; nj < 4; nj++)
#pragma unroll
            for (int q = 0; q < 4; q++) acc[mi][nj][q] = 0.0f;

    auto issue_slab = [&](int kb, int s) {
        __nv_bfloat16* st = smem + s * STAGE_ELN;
#pragma unroll
        for (int it = 0; it < 2; it++) {
            int idx = it * 256 + tid;
            int row = idx >> 2;
            int ch  = idx & 3;
            size_t go = (size_t)row * K + kb + ch * 8;
            int so = row * ROWH + ch * 8;
            cp16(st + so,                A  + (size_t)m0 * K + go);
            cp16(st + TILE_ELN + so,     BH + (size_t)n0 * K + go);
            cp16(st + 2 * TILE_ELN + so, BM + (size_t)n0 * K + go);
        }
        cp_commit();
    };

    const int nslab = K / GTK;
    issue_slab(0, 0);
    int s = 0;
    for (int sl = 0; sl < nslab; sl++) {
        if (sl + 1 < nslab) { issue_slab((sl + 1) * GTK, s ^ 1); cp_wait1(); }
        else                { cp_wait0(); }
        __syncthreads();

        const uint32_t stA  = sbase + (uint32_t)(s * STAGE_ELN) * 2;
        const uint32_t stBH = stA + TILE_ELN * 2;
        const uint32_t stBM = stBH + TILE_ELN * 2;

#pragma unroll
        for (int kc = 0; kc < 2; kc++) {
            const uint32_t kh2 = (uint32_t)(kc * 16 * 2);   // byte offset in row
            uint32_t af[4][4];
#pragma unroll
            for (int mi = 0; mi < 4; mi++)
                ldsm_x4(af[mi][0], af[mi][1], af[mi][2], af[mi][3],
                        stA + aLane + (uint32_t)(16 * mi * ROWH * 2) + kh2);

            uint32_t bf[4][2];
#pragma unroll
            for (int p = 0; p < 2; p++) {
                uint32_t r0, r1, r2, r3;
                ldsm_x4(r0, r1, r2, r3,
                        stBH + bLane + (uint32_t)(16 * p * ROWH * 2) + kh2);
                bf[2 * p][0] = r0; bf[2 * p][1] = r1;
                bf[2 * p + 1][0] = r2; bf[2 * p + 1][1] = r3;
            }
#pragma unroll
            for (int mi = 0; mi < 4; mi++)
#pragma unroll
                for (int nj = 0; nj < 4; nj++)
                    mma16816(acc[mi][nj][0], acc[mi][nj][1], acc[mi][nj][2], acc[mi][nj][3],
                             af[mi][0], af[mi][1], af[mi][2], af[mi][3],
                             bf[nj][0], bf[nj][1]);

#pragma unroll
            for (int p = 0; p < 2; p++) {
                uint32_t r0, r1, r2, r3;
                ldsm_x4(r0, r1, r2, r3,
                        stBM + bLane + (uint32_t)(16 * p * ROWH * 2) + kh2);
                bf[2 * p][0] = r0; bf[2 * p][1] = r1;
                bf[2 * p + 1][0] = r2; bf[2 * p + 1][1] = r3;
            }
#pragma unroll
            for (int mi = 0; mi < 4; mi++)
#pragma unroll
                for (int nj = 0; nj < 4; nj++)
                    mma16816(acc[mi][nj][0], acc[mi][nj][1], acc[mi][nj][2], acc[mi][nj][3],
                             af[mi][0], af[mi][1], af[mi][2], af[mi][3],
                             bf[nj][0], bf[nj][1]);
        }
        __syncthreads();
        s ^= 1;
    }

#pragma unroll
    for (int mi = 0; mi < 4; mi++)
#pragma unroll
        for (int nj = 0; nj < 4; nj++) {
            int row = m0 + wm + 16 * mi + r;
            int col = n0 + wn + 8 * nj + c2;
            *(float2*)&C[(size_t)row * N + col] =
                make_float2(acc[mi][nj][0], acc[mi][nj][1]);
            *(float2*)&C[(size_t)(row + 8) * N + col] =
                make_float2(acc[mi][nj][2], acc[mi][nj][3]);
        }
}

// ---------------- K3: LIF scan + flagging -----------------------------------
__global__ __launch_bounds__(256) void k_lif() {
    int i = blockIdx.x * blockDim.x + threadIdx.x;
    if (i >= NB * NHID) return;
    int b = i >> 11, h = i & (NHID - 1);
    float v = 0.0f;
    uint32_t m = 0;
    bool flag = false;
#pragma unroll
    for (int t = 0; t < NT; t++) {
        float hv = g_H[(size_t)(t * NB + b) * NHID + h];
        v = __fadd_rn(__fmul_rn(v, 0.3f), hv);
        flag |= fabsf(v - 1.0f) < MARGIN_V;
        if (v >= 1.0f) { m |= (1u << t); v = 0.0f; }
    }
    g_smask[i] = (uint16_t)m;
    const __nv_bfloat16 one = __float2bfloat16(1.0f);
    const __nv_bfloat16 zero = __float2bfloat16(0.0f);
#pragma unroll
    for (int t = 0; t < NT; t++)
        g_S[(size_t)(t * NB + b) * NHID + h] = ((m >> t) & 1u) ? one : zero;
    if (flag) {
        int pos = atomicAdd(&g_nflagS, 1);
        if (pos < CAPS) g_flagS[pos] = i;
    }
}

// one-pass exact recompute of flagged (b,h)
__global__ __launch_bounds__(128) void k_fixS(const float* __restrict__ W_in) {
    int idx = blockIdx.x * blockDim.x + threadIdx.x;
    int n = g_nflagS; if (n > CAPS) n = CAPS;
    if (idx >= n) return;
    int i = g_flagS[idx];
    int b = i >> 11, h = i & (NHID - 1);
    const uint16_t* mrow = g_jmask + (size_t)b * NIN;
    const float* wrow = W_in + (size_t)h * NIN;
    float acc[NT];
#pragma unroll
    for (int t = 0; t < NT; t++) acc[t] = 0.0f;
    for (int j = 0; j < NIN; j++) {
        float w = wrow[j];
        uint32_t mk = mrow[j];
#pragma unroll
        for (int t = 0; t < NT; t++)
            acc[t] = __fadd_rn(acc[t], ((mk >> t) & 1u) ? w : 0.0f);
    }
    float v = 0.0f;
    uint32_t m = 0;
#pragma unroll
    for (int t = 0; t < NT; t++) {
        v = __fadd_rn(__fmul_rn(v, 0.3f), acc[t]);
        if (v >= 1.0f) { m |= (1u << t); v = 0.0f; }
    }
    g_smask[i] = (uint16_t)m;
    const __nv_bfloat16 one = __float2bfloat16(1.0f);
    const __nv_bfloat16 zero = __float2bfloat16(0.0f);
#pragma unroll
    for (int t = 0; t < NT; t++)
        g_S[(size_t)(t * NB + b) * NHID + h] = ((m >> t) & 1u) ? one : zero;
}

// ---------------- output flag + exact fix + count ---------------------------
__global__ __launch_bounds__(256) void k_flagO(const float* __restrict__ b_out) {
    int i = blockIdx.x * blockDim.x + threadIdx.x;
    if (i >= NM * NOUT) return;
    float val = __fadd_rn(g_O[i], b_out[i & (NOUT - 1)]);
    if (fabsf(val) < MARGIN_O) {
        int pos = atomicAdd(&g_nflagO, 1);
        if (pos < CAPO) g_flagO[pos] = i;
    }
}

__global__ __launch_bounds__(256) void k_fixO(const float* __restrict__ W_out) {
    int idx = blockIdx.x * blockDim.x + threadIdx.x;
    int n = g_nflagO; if (n > CAPO) n = CAPO;
    if (idx >= n) return;
    int i = g_flagO[idx];
    int m = i / NOUT, o = i - m * NOUT;
    int b = m & (NB - 1), t = m / NB;
    const uint16_t* srow = g_smask + (size_t)b * NHID;
    const float* wrow = W_out + (size_t)o * NHID;
    float acc = 0.0f;
    for (int h = 0; h < NHID; h++) {
        float w = wrow[h];
        acc = __fadd_rn(acc, ((srow[h] >> t) & 1u) ? w : 0.0f);
    }
    g_O[i] = acc;
}

__global__ __launch_bounds__(256) void k_count(const float* __restrict__ b_out,
                                               float* __restrict__ out) {
    int i = blockIdx.x * blockDim.x + threadIdx.x;
    if (i >= NB * NOUT) return;
    float bo = b_out[i & (NOUT - 1)];
    float s = 0.0f;
#pragma unroll
    for (int t = 0; t < NT; t++) {
        float val = __fadd_rn(g_O[(size_t)t * (NB * NOUT) + i], bo);
        s += (val > 0.0f) ? 1.0f : 0.0f;
    }
    out[i] = s;
}

// ---------------- launch ----------------------------------------------------
extern "C" void kernel_launch(void* const* d_in, const int* in_sizes, int n_in,
                              void* d_out, int out_size) {
    const float* x     = (const float*)d_in[0];
    const float* W_in  = (const float*)d_in[1];
    const float* W_out = (const float*)d_in[2];
    const float* b_out = (const float*)d_in[3];
    float* out = (float*)d_out;

    static bool attr_set = false;
    if (!attr_set) {
        cudaFuncSetAttribute(gemm_mma, cudaFuncAttributeMaxDynamicSharedMemorySize,
                             SMEM_BYTES);
        attr_set = true;
    }

    void *p_Pre, *p_S, *p_WiH, *p_WiM, *p_WoH, *p_WoM, *p_H, *p_O;
    cudaGetSymbolAddress(&p_Pre, g_Pre);
    cudaGetSymbolAddress(&p_S,   g_S);
    cudaGetSymbolAddress(&p_WiH, g_WinHi);
    cudaGetSymbolAddress(&p_WiM, g_WinMid);
    cudaGetSymbolAddress(&p_WoH, g_WoutHi);
    cudaGetSymbolAddress(&p_WoM, g_WoutMid);
    cudaGetSymbolAddress(&p_H,   g_H);
    cudaGetSymbolAddress(&p_O,   g_O);

    k_setup<<<1, 32>>>();                                            // #1
    k_limbs2<<<(NHID * NIN + NOUT * NHID + 255) / 256, 256>>>(W_in, W_out); // #2
    k_gen<<<(NB * NIN + 255) / 256, 256>>>(x);                       // #3

    {   // #4 (ncu-captured): H = PRE @ W_in^T
        dim3 grid(NHID / 128, NM / 128);
        gemm_mma<<<grid, 256, SMEM_BYTES>>>((const __nv_bfloat16*)p_Pre,
            (const __nv_bfloat16*)p_WiH, (const __nv_bfloat16*)p_WiM,
            (float*)p_H, NM, NHID, NIN);
    }

    k_lif<<<(NB * NHID + 255) / 256, 256>>>();                       // #5
    k_fixS<<<(CAPS + 127) / 128, 128>>>(W_in);                       // #6

    {   // #7: O = S @ W_out^T
        dim3 grid(NOUT / 128, NM / 128);
        gemm_mma<<<grid, 256, SMEM_BYTES>>>((const __nv_bfloat16*)p_S,
            (const __nv_bfloat16*)p_WoH, (const __nv_bfloat16*)p_WoM,
            (float*)p_O, NM, NOUT, NHID);
    }

    k_flagO<<<(NM * NOUT + 255) / 256, 256>>>(b_out);                // #8
    k_fixO<<<(CAPO + 255) / 256, 256>>>(W_out);                      // #9
    k_count<<<(NB * NOUT + 255) / 256, 256>>>(b_out, out);           // #10
}

// round 10
// speedup vs baseline: 1.1579x; 1.1479x over previous
#include <cuda_runtime.h>
#include <cuda_fp16.h>
#include <cstdint>

// ============================================================================
// SpikingNetwork, T=10. B=512, input=3072, hidden=2048, out=512
// fp16 single-limb mma.sync GEMMs (spikes exactly 1.0 in fp16 -> products
// exact; weight rounding ~2e-4 rms) + wide-margin flagging + exact fp32
// recompute (reference order) of flagged elements.
// R10: R9 GEMM (LDSM + 2-stage cp.async) with single fp16 B limb; fixS split
// back to (pair,t)-parallel form (R4-proven) for broadcast-coalesced fixups.
// Margins/f16 scheme verified rel_err==0.0 in R6.
// ============================================================================

#define NB   512
#define NIN  3072
#define NHID 2048
#define NOUT 512
#define NT   10
#define NM   (NT * NB)     // 5120

#define MARGIN_V 3.0e-3f
#define MARGIN_O 2.5e-3f
#define CAPS 131072
#define CAPO 131072

__device__ __align__(16) __half g_Pre [NM * NIN];
__device__ __align__(16) __half g_S   [NM * NHID];
__device__ __align__(16) __half g_WinH [NHID * NIN];
__device__ __align__(16) __half g_WoutH[NOUT * NHID];
__device__ float    g_H[NM * NHID];
__device__ float    g_O[NM * NOUT];
__device__ uint16_t g_jmask[NB * NIN];
__device__ uint16_t g_smask[NB * NHID];
__device__ uint32_t g_k0[NT];
__device__ uint32_t g_k1[NT];
__device__ int      g_nflagS;
__device__ int      g_flagS[CAPS];
__device__ float    g_fixH[CAPS * NT];
__device__ int      g_nflagO;
__device__ int      g_flagO[CAPO];

// ---------------- threefry2x32 (JAX-exact, 20 rounds) -----------------------
__device__ __forceinline__ uint32_t rotl32(uint32_t x, int r) {
    return __funnelshift_l(x, x, r);
}
__device__ __forceinline__ void threefry2x32(uint32_t k0, uint32_t k1,
                                             uint32_t x0, uint32_t x1,
                                             uint32_t& o0, uint32_t& o1) {
    uint32_t ks2 = k0 ^ k1 ^ 0x1BD11BDAu;
    x0 += k0; x1 += k1;
#define TF_R(r) { x0 += x1; x1 = rotl32(x1, (r)); x1 ^= x0; }
    TF_R(13) TF_R(15) TF_R(26) TF_R(6)
    x0 += k1;  x1 += ks2 + 1u;
    TF_R(17) TF_R(29) TF_R(16) TF_R(24)
    x0 += ks2; x1 += k0 + 2u;
    TF_R(13) TF_R(15) TF_R(26) TF_R(6)
    x0 += k0;  x1 += k1 + 3u;
    TF_R(17) TF_R(29) TF_R(16) TF_R(24)
    x0 += k1;  x1 += ks2 + 4u;
    TF_R(13) TF_R(15) TF_R(26) TF_R(6)
    x0 += ks2; x1 += k0 + 5u;
#undef TF_R
    o0 = x0; o1 = x1;
}

// ---------------- XLA logistic ----------------------------------------------
__device__ __forceinline__ float xla_tanh_f32(float x) {
    const float kClamp = 7.90531110763549805f;
    float ax = fabsf(x);
    float xc = fminf(fmaxf(x, -kClamp), kClamp);
    float x2 = __fmul_rn(xc, xc);
    float p;
    p = __fadd_rn(__fmul_rn(x2, -2.76076847742355e-16f), 2.00018790482477e-13f);
    p = __fadd_rn(__fmul_rn(x2, p), -8.60467152213735e-11f);
    p = __fadd_rn(__fmul_rn(x2, p),  5.12229709037114e-08f);
    p = __fadd_rn(__fmul_rn(x2, p),  1.48572235717979e-05f);
    p = __fadd_rn(__fmul_rn(x2, p),  6.37261928875436e-04f);
    p = __fadd_rn(__fmul_rn(x2, p),  4.89352455891786e-03f);
    p = __fmul_rn(xc, p);
    float q;
    q = __fadd_rn(__fmul_rn(x2, 1.19825839466702e-06f), 1.18534705686654e-04f);
    q = __fadd_rn(__fmul_rn(x2, q), 2.26843463243900e-03f);
    q = __fadd_rn(__fmul_rn(x2, q), 4.89352518554385e-03f);
    float t = __fdiv_rn(p, q);
    return (ax < 0.0004f) ? x : t;
}
__device__ __forceinline__ float xla_sigmoid_f32(float x) {
    float t = xla_tanh_f32(__fmul_rn(x, 0.5f));
    return __fadd_rn(0.5f, __fmul_rn(0.5f, t));
}

// ---------------- cp.async / ldmatrix ---------------------------------------
__device__ __forceinline__ void cp16(void* dst_smem, const void* src) {
    uint32_t d = (uint32_t)__cvta_generic_to_shared(dst_smem);
    asm volatile("cp.async.cg.shared.global [%0], [%1], 16;\n" :: "r"(d), "l"(src));
}
__device__ __forceinline__ void cp_commit() { asm volatile("cp.async.commit_group;\n"); }
__device__ __forceinline__ void cp_wait1()  { asm volatile("cp.async.wait_group 1;\n"); }
__device__ __forceinline__ void cp_wait0()  { asm volatile("cp.async.wait_group 0;\n"); }

__device__ __forceinline__ void ldsm_x4(uint32_t& r0, uint32_t& r1,
                                        uint32_t& r2, uint32_t& r3, uint32_t addr) {
    asm volatile("ldmatrix.sync.aligned.m8n8.x4.shared.b16 {%0,%1,%2,%3}, [%4];"
                 : "=r"(r0), "=r"(r1), "=r"(r2), "=r"(r3) : "r"(addr));
}

// ---------------- fp16 mma m16n8k16 -----------------------------------------
__device__ __forceinline__ void mma16816(float& d0, float& d1, float& d2, float& d3,
                                         uint32_t a0, uint32_t a1, uint32_t a2, uint32_t a3,
                                         uint32_t b0, uint32_t b1) {
    asm volatile(
        "mma.sync.aligned.m16n8k16.row.col.f32.f16.f16.f32 "
        "{%0,%1,%2,%3},{%4,%5,%6,%7},{%8,%9},{%0,%1,%2,%3};"
        : "+f"(d0), "+f"(d1), "+f"(d2), "+f"(d3)
        : "r"(a0), "r"(a1), "r"(a2), "r"(a3), "r"(b0), "r"(b1));
}

// ---------------- setup (launch #1) -----------------------------------------
__global__ void k_setup() {
    int t = threadIdx.x;
    if (t == 0) { g_nflagS = 0; g_nflagO = 0; }
    if (t < NT) {
        uint32_t a, b;
        threefry2x32(0u, 42u, 0u, (uint32_t)t, a, b);
        g_k0[t] = a; g_k1[t] = b;
    }
}

// both weight fp16 casts (launch #2)
__global__ __launch_bounds__(256) void k_half2(const float* __restrict__ Wi,
                                               const float* __restrict__ Wo) {
    int i = blockIdx.x * blockDim.x + threadIdx.x;
    const int n1 = NHID * NIN;
    const int n2 = NOUT * NHID;
    if (i >= n1 + n2) return;
    if (i < n1) g_WinH[i] = __float2half_rn(Wi[i]);
    else        g_WoutH[i - n1] = __float2half_rn(Wo[i - n1]);
}

// ---------------- K1: stochastic input spikes (launch #3) -------------------
__global__ __launch_bounds__(256) void k_gen(const float* __restrict__ x) {
    int idx = blockIdx.x * blockDim.x + threadIdx.x;
    if (idx >= NB * NIN) return;
    int b = idx / NIN, j = idx - b * NIN;
    float p = xla_sigmoid_f32(x[idx]);
    uint32_t m = 0;
#pragma unroll
    for (int t = 0; t < NT; t++) {
        uint32_t a, bb;
        threefry2x32(g_k0[t], g_k1[t], 0u, (uint32_t)idx, a, bb);
        uint32_t bits = a ^ bb;
        float u = __uint_as_float((bits >> 9) | 0x3F800000u) - 1.0f;
        m |= (u < p) ? (1u << t) : 0u;
    }
    g_jmask[idx] = (uint16_t)m;
    const __half one = __float2half(1.0f);
    const __half zero = __float2half(0.0f);
#pragma unroll
    for (int t = 0; t < NT; t++)
        g_Pre[(size_t)(t * NB + b) * NIN + j] = ((m >> t) & 1u) ? one : zero;
}

// ---------------- fp16 tensor-core GEMM (launch #4) -------------------------
// C[m][n] = sum_k A[m][k]*B[n][k]; CTA 128x128x32, 8 warps, warp 64x32,
// m16n8k16, 2-stage cp.async pipeline, ldmatrix.x4 fragment loads.
#define GTK 32
#define ROWH 40                             // halves per smem row (80B stride)
#define NSTG 2
#define TILE_ELN (128 * ROWH)
#define STAGE_ELN (2 * TILE_ELN)            // A + B per stage
#define SMEM_BYTES (NSTG * STAGE_ELN * 2)   // 40960

__global__ __launch_bounds__(256)
void gemm_mma(const __half* __restrict__ A,
              const __half* __restrict__ B,
              float* __restrict__ C, int M, int N, int K) {
    extern __shared__ __half smem[];

    const int tid  = threadIdx.x;
    const int m0   = blockIdx.y * 128;
    const int n0   = blockIdx.x * 128;
    const int warp = tid >> 5;
    const int lane = tid & 31;
    const int wm   = (warp & 1) * 64;
    const int wn   = (warp >> 1) * 32;
    const int r    = lane >> 2;
    const int c2   = (lane & 3) * 2;

    const uint32_t sbase = (uint32_t)__cvta_generic_to_shared(smem);
    const uint32_t aLane = (uint32_t)(((wm + (lane & 15)) * ROWH + ((lane >> 4) * 8)) * 2);
    const uint32_t bLane = (uint32_t)(((wn + 8 * (lane >> 4) + (lane & 7)) * ROWH
                                       + (((lane >> 3) & 1) * 8)) * 2);

    float acc[4][4][4];
#pragma unroll
    for (int mi = 0; mi < 4; mi++)
#pragma unroll
        for (int nj = 0; nj < 4; nj++)
#pragma unroll
            for (int q = 0; q < 4; q++) acc[mi][nj][q] = 0.0f;

    auto issue_slab = [&](int kb, int s) {
        __half* st = smem + s * STAGE_ELN;
#pragma unroll
        for (int it = 0; it < 2; it++) {
            int idx = it * 256 + tid;
            int row = idx >> 2;
            int ch  = idx & 3;
            size_t go = (size_t)row * K + kb + ch * 8;
            int so = row * ROWH + ch * 8;
            cp16(st + so,            A + (size_t)m0 * K + go);
            cp16(st + TILE_ELN + so, B + (size_t)n0 * K + go);
        }
        cp_commit();
    };

    const int nslab = K / GTK;
    issue_slab(0, 0);
    int s = 0;
    for (int sl = 0; sl < nslab; sl++) {
        if (sl + 1 < nslab) { issue_slab((sl + 1) * GTK, s ^ 1); cp_wait1(); }
        else                { cp_wait0(); }
        __syncthreads();

        const uint32_t stA = sbase + (uint32_t)(s * STAGE_ELN) * 2;
        const uint32_t stB = stA + TILE_ELN * 2;

#pragma unroll
        for (int kc = 0; kc < 2; kc++) {
            const uint32_t kh2 = (uint32_t)(kc * 16 * 2);
            uint32_t af[4][4];
#pragma unroll
            for (int mi = 0; mi < 4; mi++)
                ldsm_x4(af[mi][0], af[mi][1], af[mi][2], af[mi][3],
                        stA + aLane + (uint32_t)(16 * mi * ROWH * 2) + kh2);

            uint32_t bf[4][2];
#pragma unroll
            for (int p = 0; p < 2; p++) {
                uint32_t r0, r1, r2, r3;
                ldsm_x4(r0, r1, r2, r3,
                        stB + bLane + (uint32_t)(16 * p * ROWH * 2) + kh2);
                bf[2 * p][0] = r0; bf[2 * p][1] = r1;
                bf[2 * p + 1][0] = r2; bf[2 * p + 1][1] = r3;
            }
#pragma unroll
            for (int mi = 0; mi < 4; mi++)
#pragma unroll
                for (int nj = 0; nj < 4; nj++)
                    mma16816(acc[mi][nj][0], acc[mi][nj][1], acc[mi][nj][2], acc[mi][nj][3],
                             af[mi][0], af[mi][1], af[mi][2], af[mi][3],
                             bf[nj][0], bf[nj][1]);
        }
        __syncthreads();
        s ^= 1;
    }

#pragma unroll
    for (int mi = 0; mi < 4; mi++)
#pragma unroll
        for (int nj = 0; nj < 4; nj++) {
            int row = m0 + wm + 16 * mi + r;
            int col = n0 + wn + 8 * nj + c2;
            *(float2*)&C[(size_t)row * N + col] =
                make_float2(acc[mi][nj][0], acc[mi][nj][1]);
            *(float2*)&C[(size_t)(row + 8) * N + col] =
                make_float2(acc[mi][nj][2], acc[mi][nj][3]);
        }
}

// ---------------- K3: LIF scan + flagging -----------------------------------
__global__ __launch_bounds__(256) void k_lif() {
    int i = blockIdx.x * blockDim.x + threadIdx.x;
    if (i >= NB * NHID) return;
    int b = i >> 11, h = i & (NHID - 1);
    float v = 0.0f;
    uint32_t m = 0;
    bool flag = false;
#pragma unroll
    for (int t = 0; t < NT; t++) {
        float hv = g_H[(size_t)(t * NB + b) * NHID + h];
        v = __fadd_rn(__fmul_rn(v, 0.3f), hv);
        flag |= fabsf(v - 1.0f) < MARGIN_V;
        if (v >= 1.0f) { m |= (1u << t); v = 0.0f; }
    }
    g_smask[i] = (uint16_t)m;
    const __half one = __float2half(1.0f);
    const __half zero = __float2half(0.0f);
#pragma unroll
    for (int t = 0; t < NT; t++)
        g_S[(size_t)(t * NB + b) * NHID + h] = ((m >> t) & 1u) ? one : zero;
    if (flag) {
        int pos = atomicAdd(&g_nflagS, 1);
        if (pos < CAPS) g_flagS[pos] = i;
    }
}

// exact h for flagged pairs: one thread per (pair, t); the NT threads of a
// pair read the same W row -> broadcast-coalesced. Ascending-j fp32 chain.
__global__ __launch_bounds__(256) void k_fixS1(const float* __restrict__ W_in) {
    int idx = blockIdx.x * blockDim.x + threadIdx.x;
    int n = g_nflagS; if (n > CAPS) n = CAPS;
    int pr = idx / NT, t = idx - pr * NT;
    if (pr >= n) return;
    int i = g_flagS[pr];
    int b = i >> 11, h = i & (NHID - 1);
    const uint16_t* mrow = g_jmask + (size_t)b * NIN;
    const float* wrow = W_in + (size_t)h * NIN;
    float acc = 0.0f;
    for (int j = 0; j < NIN; j++) {
        float w = wrow[j];
        acc = __fadd_rn(acc, ((mrow[j] >> t) & 1u) ? w : 0.0f);
    }
    g_fixH[pr * NT + t] = acc;
}

// exact v-chain + spike rewrite for flagged pairs
__global__ __launch_bounds__(256) void k_fixS2() {
    int idx = blockIdx.x * blockDim.x + threadIdx.x;
    int n = g_nflagS; if (n > CAPS) n = CAPS;
    if (idx >= n) return;
    int i = g_flagS[idx];
    int b = i >> 11, h = i & (NHID - 1);
    float v = 0.0f;
    uint32_t m = 0;
#pragma unroll
    for (int t = 0; t < NT; t++) {
        v = __fadd_rn(__fmul_rn(v, 0.3f), g_fixH[idx * NT + t]);
        if (v >= 1.0f) { m |= (1u << t); v = 0.0f; }
    }
    g_smask[i] = (uint16_t)m;
    const __half one = __float2half(1.0f);
    const __half zero = __float2half(0.0f);
#pragma unroll
    for (int t = 0; t < NT; t++)
        g_S[(size_t)(t * NB + b) * NHID + h] = ((m >> t) & 1u) ? one : zero;
}

// ---------------- output flag + exact fix + count ---------------------------
__global__ __launch_bounds__(256) void k_flagO(const float* __restrict__ b_out) {
    int i = blockIdx.x * blockDim.x + threadIdx.x;
    if (i >= NM * NOUT) return;
    float val = __fadd_rn(g_O[i], b_out[i & (NOUT - 1)]);
    if (fabsf(val) < MARGIN_O) {
        int pos = atomicAdd(&g_nflagO, 1);
        if (pos < CAPO) g_flagO[pos] = i;
    }
}

__global__ __launch_bounds__(256) void k_fixO(const float* __restrict__ W_out) {
    int idx = blockIdx.x * blockDim.x + threadIdx.x;
    int n = g_nflagO; if (n > CAPO) n = CAPO;
    if (idx >= n) return;
    int i = g_flagO[idx];
    int m = i / NOUT, o = i - m * NOUT;
    int b = m & (NB - 1), t = m / NB;
    const uint16_t* srow = g_smask + (size_t)b * NHID;
    const float* wrow = W_out + (size_t)o * NHID;
    float acc = 0.0f;
    for (int h = 0; h < NHID; h++) {
        float w = wrow[h];
        acc = __fadd_rn(acc, ((srow[h] >> t) & 1u) ? w : 0.0f);
    }
    g_O[i] = acc;
}

__global__ __launch_bounds__(256) void k_count(const float* __restrict__ b_out,
                                               float* __restrict__ out) {
    int i = blockIdx.x * blockDim.x + threadIdx.x;
    if (i >= NB * NOUT) return;
    float bo = b_out[i & (NOUT - 1)];
    float s = 0.0f;
#pragma unroll
    for (int t = 0; t < NT; t++) {
        float val = __fadd_rn(g_O[(size_t)t * (NB * NOUT) + i], bo);
        s += (val > 0.0f) ? 1.0f : 0.0f;
    }
    out[i] = s;
}

// ---------------- launch ----------------------------------------------------
extern "C" void kernel_launch(void* const* d_in, const int* in_sizes, int n_in,
                              void* d_out, int out_size) {
    const float* x     = (const float*)d_in[0];
    const float* W_in  = (const float*)d_in[1];
    const float* W_out = (const float*)d_in[2];
    const float* b_out = (const float*)d_in[3];
    float* out = (float*)d_out;

    static bool attr_set = false;
    if (!attr_set) {
        cudaFuncSetAttribute(gemm_mma, cudaFuncAttributeMaxDynamicSharedMemorySize,
                             SMEM_BYTES);
        attr_set = true;
    }

    void *p_Pre, *p_S, *p_WiH, *p_WoH, *p_H, *p_O;
    cudaGetSymbolAddress(&p_Pre, g_Pre);
    cudaGetSymbolAddress(&p_S,   g_S);
    cudaGetSymbolAddress(&p_WiH, g_WinH);
    cudaGetSymbolAddress(&p_WoH, g_WoutH);
    cudaGetSymbolAddress(&p_H,   g_H);
    cudaGetSymbolAddress(&p_O,   g_O);

    k_setup<<<1, 32>>>();                                            // #1
    k_half2<<<(NHID * NIN + NOUT * NHID + 255) / 256, 256>>>(W_in, W_out); // #2
    k_gen<<<(NB * NIN + 255) / 256, 256>>>(x);                       // #3

    {   // #4 (ncu-captured): H = PRE @ W_in^T
        dim3 grid(NHID / 128, NM / 128);
        gemm_mma<<<grid, 256, SMEM_BYTES>>>((const __half*)p_Pre,
            (const __half*)p_WiH, (float*)p_H, NM, NHID, NIN);
    }

    k_lif<<<(NB * NHID + 255) / 256, 256>>>();                       // #5
    k_fixS1<<<(CAPS * NT + 255) / 256, 256>>>(W_in);                 // #6
    k_fixS2<<<(CAPS + 255) / 256, 256>>>();                          // #7

    {   // #8: O = S @ W_out^T
        dim3 grid(NOUT / 128, NM / 128);
        gemm_mma<<<grid, 256, SMEM_BYTES>>>((const __half*)p_S,
            (const __half*)p_WoH, (float*)p_O, NM, NOUT, NHID);
    }

    k_flagO<<<(NM * NOUT + 255) / 256, 256>>>(b_out);                // #9
    k_fixO<<<(CAPO + 255) / 256, 256>>>(W_out);                      // #10
    k_count<<<(NB * NOUT + 255) / 256, 256>>>(b_out, out);           // #11
}

// round 11
// speedup vs baseline: 1.5334x; 1.3243x over previous
#include <cuda_runtime.h>
#include <cuda_fp16.h>
#include <cstdint>

// ============================================================================
// SpikingNetwork, T=10. B=512, input=3072, hidden=2048, out=512
// fp16 single-limb mma.sync GEMMs + margin flagging + exact fp32 recompute.
// R11: GTK=64 slabs (half the barriers, deeper prefetch cover), margins
// tightened to 2e-3/1.5e-3 (>=10 sigma of the fp16-residual error model),
// vectorized fixS1 (float4 W + uint64 mask loads).
// ============================================================================

#define NB   512
#define NIN  3072
#define NHID 2048
#define NOUT 512
#define NT   10
#define NM   (NT * NB)     // 5120

#define MARGIN_V 2.0e-3f
#define MARGIN_O 1.5e-3f
#define CAPS 131072
#define CAPO 131072

__device__ __align__(16) __half g_Pre [NM * NIN];
__device__ __align__(16) __half g_S   [NM * NHID];
__device__ __align__(16) __half g_WinH [NHID * NIN];
__device__ __align__(16) __half g_WoutH[NOUT * NHID];
__device__ float    g_H[NM * NHID];
__device__ float    g_O[NM * NOUT];
__device__ __align__(8) uint16_t g_jmask[NB * NIN];
__device__ uint16_t g_smask[NB * NHID];
__device__ uint32_t g_k0[NT];
__device__ uint32_t g_k1[NT];
__device__ int      g_nflagS;
__device__ int      g_flagS[CAPS];
__device__ float    g_fixH[CAPS * NT];
__device__ int      g_nflagO;
__device__ int      g_flagO[CAPO];

// ---------------- threefry2x32 (JAX-exact, 20 rounds) -----------------------
__device__ __forceinline__ uint32_t rotl32(uint32_t x, int r) {
    return __funnelshift_l(x, x, r);
}
__device__ __forceinline__ void threefry2x32(uint32_t k0, uint32_t k1,
                                             uint32_t x0, uint32_t x1,
                                             uint32_t& o0, uint32_t& o1) {
    uint32_t ks2 = k0 ^ k1 ^ 0x1BD11BDAu;
    x0 += k0; x1 += k1;
#define TF_R(r) { x0 += x1; x1 = rotl32(x1, (r)); x1 ^= x0; }
    TF_R(13) TF_R(15) TF_R(26) TF_R(6)
    x0 += k1;  x1 += ks2 + 1u;
    TF_R(17) TF_R(29) TF_R(16) TF_R(24)
    x0 += ks2; x1 += k0 + 2u;
    TF_R(13) TF_R(15) TF_R(26) TF_R(6)
    x0 += k0;  x1 += k1 + 3u;
    TF_R(17) TF_R(29) TF_R(16) TF_R(24)
    x0 += k1;  x1 += ks2 + 4u;
    TF_R(13) TF_R(15) TF_R(26) TF_R(6)
    x0 += ks2; x1 += k0 + 5u;
#undef TF_R
    o0 = x0; o1 = x1;
}

// ---------------- XLA logistic ----------------------------------------------
__device__ __forceinline__ float xla_tanh_f32(float x) {
    const float kClamp = 7.90531110763549805f;
    float ax = fabsf(x);
    float xc = fminf(fmaxf(x, -kClamp), kClamp);
    float x2 = __fmul_rn(xc, xc);
    float p;
    p = __fadd_rn(__fmul_rn(x2, -2.76076847742355e-16f), 2.00018790482477e-13f);
    p = __fadd_rn(__fmul_rn(x2, p), -8.60467152213735e-11f);
    p = __fadd_rn(__fmul_rn(x2, p),  5.12229709037114e-08f);
    p = __fadd_rn(__fmul_rn(x2, p),  1.48572235717979e-05f);
    p = __fadd_rn(__fmul_rn(x2, p),  6.37261928875436e-04f);
    p = __fadd_rn(__fmul_rn(x2, p),  4.89352455891786e-03f);
    p = __fmul_rn(xc, p);
    float q;
    q = __fadd_rn(__fmul_rn(x2, 1.19825839466702e-06f), 1.18534705686654e-04f);
    q = __fadd_rn(__fmul_rn(x2, q), 2.26843463243900e-03f);
    q = __fadd_rn(__fmul_rn(x2, q), 4.89352518554385e-03f);
    float t = __fdiv_rn(p, q);
    return (ax < 0.0004f) ? x : t;
}
__device__ __forceinline__ float xla_sigmoid_f32(float x) {
    float t = xla_tanh_f32(__fmul_rn(x, 0.5f));
    return __fadd_rn(0.5f, __fmul_rn(0.5f, t));
}

// ---------------- cp.async / ldmatrix ---------------------------------------
__device__ __forceinline__ void cp16(void* dst_smem, const void* src) {
    uint32_t d = (uint32_t)__cvta_generic_to_shared(dst_smem);
    asm volatile("cp.async.cg.shared.global [%0], [%1], 16;\n" :: "r"(d), "l"(src));
}
__device__ __forceinline__ void cp_commit() { asm volatile("cp.async.commit_group;\n"); }
__device__ __forceinline__ void cp_wait1()  { asm volatile("cp.async.wait_group 1;\n"); }
__device__ __forceinline__ void cp_wait0()  { asm volatile("cp.async.wait_group 0;\n"); }

__device__ __forceinline__ void ldsm_x4(uint32_t& r0, uint32_t& r1,
                                        uint32_t& r2, uint32_t& r3, uint32_t addr) {
    asm volatile("ldmatrix.sync.aligned.m8n8.x4.shared.b16 {%0,%1,%2,%3}, [%4];"
                 : "=r"(r0), "=r"(r1), "=r"(r2), "=r"(r3) : "r"(addr));
}

// ---------------- fp16 mma m16n8k16 -----------------------------------------
__device__ __forceinline__ void mma16816(float& d0, float& d1, float& d2, float& d3,
                                         uint32_t a0, uint32_t a1, uint32_t a2, uint32_t a3,
                                         uint32_t b0, uint32_t b1) {
    asm volatile(
        "mma.sync.aligned.m16n8k16.row.col.f32.f16.f16.f32 "
        "{%0,%1,%2,%3},{%4,%5,%6,%7},{%8,%9},{%0,%1,%2,%3};"
        : "+f"(d0), "+f"(d1), "+f"(d2), "+f"(d3)
        : "r"(a0), "r"(a1), "r"(a2), "r"(a3), "r"(b0), "r"(b1));
}

// ---------------- setup (launch #1) -----------------------------------------
__global__ void k_setup() {
    int t = threadIdx.x;
    if (t == 0) { g_nflagS = 0; g_nflagO = 0; }
    if (t < NT) {
        uint32_t a, b;
        threefry2x32(0u, 42u, 0u, (uint32_t)t, a, b);
        g_k0[t] = a; g_k1[t] = b;
    }
}

// both weight fp16 casts (launch #2)
__global__ __launch_bounds__(256) void k_half2(const float* __restrict__ Wi,
                                               const float* __restrict__ Wo) {
    int i = blockIdx.x * blockDim.x + threadIdx.x;
    const int n1 = NHID * NIN;
    const int n2 = NOUT * NHID;
    if (i >= n1 + n2) return;
    if (i < n1) g_WinH[i] = __float2half_rn(Wi[i]);
    else        g_WoutH[i - n1] = __float2half_rn(Wo[i - n1]);
}

// ---------------- K1: stochastic input spikes (launch #3) -------------------
__global__ __launch_bounds__(256) void k_gen(const float* __restrict__ x) {
    int idx = blockIdx.x * blockDim.x + threadIdx.x;
    if (idx >= NB * NIN) return;
    int b = idx / NIN, j = idx - b * NIN;
    float p = xla_sigmoid_f32(x[idx]);
    uint32_t m = 0;
#pragma unroll
    for (int t = 0; t < NT; t++) {
        uint32_t a, bb;
        threefry2x32(g_k0[t], g_k1[t], 0u, (uint32_t)idx, a, bb);
        uint32_t bits = a ^ bb;
        float u = __uint_as_float((bits >> 9) | 0x3F800000u) - 1.0f;
        m |= (u < p) ? (1u << t) : 0u;
    }
    g_jmask[idx] = (uint16_t)m;
    const __half one = __float2half(1.0f);
    const __half zero = __float2half(0.0f);
#pragma unroll
    for (int t = 0; t < NT; t++)
        g_Pre[(size_t)(t * NB + b) * NIN + j] = ((m >> t) & 1u) ? one : zero;
}

// ---------------- fp16 tensor-core GEMM (launch #4) -------------------------
// C[m][n] = sum_k A[m][k]*B[n][k]; CTA 128x128x64, 8 warps, warp 64x32,
// m16n8k16, 2-stage cp.async pipeline, ldmatrix.x4 fragment loads.
#define GTK 64
#define ROWH 72                             // halves per smem row (144B stride)
#define NSTG 2
#define TILE_ELN (128 * ROWH)               // 9216 halves
#define STAGE_ELN (2 * TILE_ELN)            // A + B per stage
#define SMEM_BYTES (NSTG * STAGE_ELN * 2)   // 73728

__global__ __launch_bounds__(256)
void gemm_mma(const __half* __restrict__ A,
              const __half* __restrict__ B,
              float* __restrict__ C, int M, int N, int K) {
    extern __shared__ __half smem[];

    const int tid  = threadIdx.x;
    const int m0   = blockIdx.y * 128;
    const int n0   = blockIdx.x * 128;
    const int warp = tid >> 5;
    const int lane = tid & 31;
    const int wm   = (warp & 1) * 64;
    const int wn   = (warp >> 1) * 32;
    const int r    = lane >> 2;
    const int c2   = (lane & 3) * 2;

    const uint32_t sbase = (uint32_t)__cvta_generic_to_shared(smem);
    const uint32_t aLane = (uint32_t)(((wm + (lane & 15)) * ROWH + ((lane >> 4) * 8)) * 2);
    const uint32_t bLane = (uint32_t)(((wn + 8 * (lane >> 4) + (lane & 7)) * ROWH
                                       + (((lane >> 3) & 1) * 8)) * 2);

    float acc[4][4][4];
#pragma unroll
    for (int mi = 0; mi < 4; mi++)
#pragma unroll
        for (int nj = 0; nj < 4; nj++)
#pragma unroll
            for (int q = 0; q < 4; q++) acc[mi][nj][q] = 0.0f;

    auto issue_slab = [&](int kb, int s) {
        __half* st = smem + s * STAGE_ELN;
#pragma unroll
        for (int it = 0; it < 4; it++) {
            int idx = it * 256 + tid;       // 0..1023
            int row = idx >> 3;
            int ch  = idx & 7;
            size_t go = (size_t)row * K + kb + ch * 8;
            int so = row * ROWH + ch * 8;
            cp16(st + so,            A + (size_t)m0 * K + go);
            cp16(st + TILE_ELN + so, B + (size_t)n0 * K + go);
        }
        cp_commit();
    };

    const int nslab = K / GTK;
    issue_slab(0, 0);
    int s = 0;
    for (int sl = 0; sl < nslab; sl++) {
        if (sl + 1 < nslab) { issue_slab((sl + 1) * GTK, s ^ 1); cp_wait1(); }
        else                { cp_wait0(); }
        __syncthreads();

        const uint32_t stA = sbase + (uint32_t)(s * STAGE_ELN) * 2;
        const uint32_t stB = stA + TILE_ELN * 2;

#pragma unroll
        for (int kc = 0; kc < 4; kc++) {    // four k16 steps in the 64-k slab
            const uint32_t kh2 = (uint32_t)(kc * 16 * 2);
            uint32_t af[4][4];
#pragma unroll
            for (int mi = 0; mi < 4; mi++)
                ldsm_x4(af[mi][0], af[mi][1], af[mi][2], af[mi][3],
                        stA + aLane + (uint32_t)(16 * mi * ROWH * 2) + kh2);

            uint32_t bf[4][2];
#pragma unroll
            for (int p = 0; p < 2; p++) {
                uint32_t r0, r1, r2, r3;
                ldsm_x4(r0, r1, r2, r3,
                        stB + bLane + (uint32_t)(16 * p * ROWH * 2) + kh2);
                bf[2 * p][0] = r0; bf[2 * p][1] = r1;
                bf[2 * p + 1][0] = r2; bf[2 * p + 1][1] = r3;
            }
#pragma unroll
            for (int mi = 0; mi < 4; mi++)
#pragma unroll
                for (int nj = 0; nj < 4; nj++)
                    mma16816(acc[mi][nj][0], acc[mi][nj][1], acc[mi][nj][2], acc[mi][nj][3],
                             af[mi][0], af[mi][1], af[mi][2], af[mi][3],
                             bf[nj][0], bf[nj][1]);
        }
        __syncthreads();
        s ^= 1;
    }

#pragma unroll
    for (int mi = 0; mi < 4; mi++)
#pragma unroll
        for (int nj = 0; nj < 4; nj++) {
            int row = m0 + wm + 16 * mi + r;
            int col = n0 + wn + 8 * nj + c2;
            *(float2*)&C[(size_t)row * N + col] =
                make_float2(acc[mi][nj][0], acc[mi][nj][1]);
            *(float2*)&C[(size_t)(row + 8) * N + col] =
                make_float2(acc[mi][nj][2], acc[mi][nj][3]);
        }
}

// ---------------- K3: LIF scan + flagging -----------------------------------
__global__ __launch_bounds__(256) void k_lif() {
    int i = blockIdx.x * blockDim.x + threadIdx.x;
    if (i >= NB * NHID) return;
    int b = i >> 11, h = i & (NHID - 1);
    float v = 0.0f;
    uint32_t m = 0;
    bool flag = false;
#pragma unroll
    for (int t = 0; t < NT; t++) {
        float hv = g_H[(size_t)(t * NB + b) * NHID + h];
        v = __fadd_rn(__fmul_rn(v, 0.3f), hv);
        flag |= fabsf(v - 1.0f) < MARGIN_V;
        if (v >= 1.0f) { m |= (1u << t); v = 0.0f; }
    }
    g_smask[i] = (uint16_t)m;
    const __half one = __float2half(1.0f);
    const __half zero = __float2half(0.0f);
#pragma unroll
    for (int t = 0; t < NT; t++)
        g_S[(size_t)(t * NB + b) * NHID + h] = ((m >> t) & 1u) ? one : zero;
    if (flag) {
        int pos = atomicAdd(&g_nflagS, 1);
        if (pos < CAPS) g_flagS[pos] = i;
    }
}

// exact h for flagged pairs: one thread per (pair, t); vectorized loads
// (float4 weights + uint64 masks), strict ascending-j fp32 chain.
// Skipping zero-adds is bit-exact (acc never -0).
__global__ __launch_bounds__(256) void k_fixS1(const float* __restrict__ W_in) {
    int idx = blockIdx.x * blockDim.x + threadIdx.x;
    int n = g_nflagS; if (n > CAPS) n = CAPS;
    int pr = idx / NT, t = idx - pr * NT;
    if (pr >= n) return;
    int i = g_flagS[pr];
    int b = i >> 11, h = i & (NHID - 1);
    const uint16_t* mrow = g_jmask + (size_t)b * NIN;
    const float* wrow = W_in + (size_t)h * NIN;
    float acc = 0.0f;
    for (int j = 0; j < NIN; j += 4) {
        float4 w = *(const float4*)(wrow + j);
        uint64_t mk = *(const uint64_t*)(mrow + j);
        if ((mk >> t) & 1u)        acc = __fadd_rn(acc, w.x);
        if ((mk >> (16 + t)) & 1u) acc = __fadd_rn(acc, w.y);
        if ((mk >> (32 + t)) & 1u) acc = __fadd_rn(acc, w.z);
        if ((mk >> (48 + t)) & 1u) acc = __fadd_rn(acc, w.w);
    }
    g_fixH[pr * NT + t] = acc;
}

// exact v-chain + spike rewrite for flagged pairs
__global__ __launch_bounds__(256) void k_fixS2() {
    int idx = blockIdx.x * blockDim.x + threadIdx.x;
    int n = g_nflagS; if (n > CAPS) n = CAPS;
    if (idx >= n) return;
    int i = g_flagS[idx];
    int b = i >> 11, h = i & (NHID - 1);
    float v = 0.0f;
    uint32_t m = 0;
#pragma unroll
    for (int t = 0; t < NT; t++) {
        v = __fadd_rn(__fmul_rn(v, 0.3f), g_fixH[idx * NT + t]);
        if (v >= 1.0f) { m |= (1u << t); v = 0.0f; }
    }
    g_smask[i] = (uint16_t)m;
    const __half one = __float2half(1.0f);
    const __half zero = __float2half(0.0f);
#pragma unroll
    for (int t = 0; t < NT; t++)
        g_S[(size_t)(t * NB + b) * NHID + h] = ((m >> t) & 1u) ? one : zero;
}

// ---------------- output flag + exact fix + count ---------------------------
__global__ __launch_bounds__(256) void k_flagO(const float* __restrict__ b_out) {
    int i = blockIdx.x * blockDim.x + threadIdx.x;
    if (i >= NM * NOUT) return;
    float val = __fadd_rn(g_O[i], b_out[i & (NOUT - 1)]);
    if (fabsf(val) < MARGIN_O) {
        int pos = atomicAdd(&g_nflagO, 1);
        if (pos < CAPO) g_flagO[pos] = i;
    }
}

__global__ __launch_bounds__(256) void k_fixO(const float* __restrict__ W_out) {
    int idx = blockIdx.x * blockDim.x + threadIdx.x;
    int n = g_nflagO; if (n > CAPO) n = CAPO;
    if (idx >= n) return;
    int i = g_flagO[idx];
    int m = i / NOUT, o = i - m * NOUT;
    int b = m & (NB - 1), t = m / NB;
    const uint16_t* srow = g_smask + (size_t)b * NHID;
    const float* wrow = W_out + (size_t)o * NHID;
    float acc = 0.0f;
    for (int h = 0; h < NHID; h++) {
        float w = wrow[h];
        acc = __fadd_rn(acc, ((srow[h] >> t) & 1u) ? w : 0.0f);
    }
    g_O[i] = acc;
}

__global__ __launch_bounds__(256) void k_count(const float* __restrict__ b_out,
                                               float* __restrict__ out) {
    int i = blockIdx.x * blockDim.x + threadIdx.x;
    if (i >= NB * NOUT) return;
    float bo = b_out[i & (NOUT - 1)];
    float s = 0.0f;
#pragma unroll
    for (int t = 0; t < NT; t++) {
        float val = __fadd_rn(g_O[(size_t)t * (NB * NOUT) + i], bo);
        s += (val > 0.0f) ? 1.0f : 0.0f;
    }
    out[i] = s;
}

// ---------------- launch ----------------------------------------------------
extern "C" void kernel_launch(void* const* d_in, const int* in_sizes, int n_in,
                              void* d_out, int out_size) {
    const float* x     = (const float*)d_in[0];
    const float* W_in  = (const float*)d_in[1];
    const float* W_out = (const float*)d_in[2];
    const float* b_out = (const float*)d_in[3];
    float* out = (float*)d_out;

    static bool attr_set = false;
    if (!attr_set) {
        cudaFuncSetAttribute(gemm_mma, cudaFuncAttributeMaxDynamicSharedMemorySize,
                             SMEM_BYTES);
        attr_set = true;
    }

    void *p_Pre, *p_S, *p_WiH, *p_WoH, *p_H, *p_O;
    cudaGetSymbolAddress(&p_Pre, g_Pre);
    cudaGetSymbolAddress(&p_S,   g_S);
    cudaGetSymbolAddress(&p_WiH, g_WinH);
    cudaGetSymbolAddress(&p_WoH, g_WoutH);
    cudaGetSymbolAddress(&p_H,   g_H);
    cudaGetSymbolAddress(&p_O,   g_O);

    k_setup<<<1, 32>>>();                                            // #1
    k_half2<<<(NHID * NIN + NOUT * NHID + 255) / 256, 256>>>(W_in, W_out); // #2
    k_gen<<<(NB * NIN + 255) / 256, 256>>>(x);                       // #3

    {   // #4 (ncu-captured): H = PRE @ W_in^T
        dim3 grid(NHID / 128, NM / 128);
        gemm_mma<<<grid, 256, SMEM_BYTES>>>((const __half*)p_Pre,
            (const __half*)p_WiH, (float*)p_H, NM, NHID, NIN);
    }

    k_lif<<<(NB * NHID + 255) / 256, 256>>>();                       // #5
    k_fixS1<<<(CAPS * NT + 255) / 256, 256>>>(W_in);                 // #6
    k_fixS2<<<(CAPS + 255) / 256, 256>>>();                          // #7

    {   // #8: O = S @ W_out^T
        dim3 grid(NOUT / 128, NM / 128);
        gemm_mma<<<grid, 256, SMEM_BYTES>>>((const __half*)p_S,
            (const __half*)p_WoH, (float*)p_O, NM, NOUT, NHID);
    }

    k_flagO<<<(NM * NOUT + 255) / 256, 256>>>(b_out);                // #9
    k_fixO<<<(CAPO + 255) / 256, 256>>>(W_out);                      // #10
    k_count<<<(NB * NOUT + 255) / 256, 256>>>(b_out, out);           // #11
}